// round 1
// baseline (speedup 1.0000x reference)
#include <cuda_runtime.h>
#include <math.h>

#define OPACITY_TH 0.01f
#define EARLY_TERM 1e-4f

// shared-memory float offsets
#define OFF_W1   0        // f_w1 [3][128]
#define OFF_B1   384      // f_b1 [128]
#define OFF_W2   512      // f_w2 [128][64]
#define OFF_B2   8704     // f_b2 [64]
#define OFF_SW   8768     // s_w  [64]
#define OFF_SB   8832     // s_b  [1]  (+3 pad)
#define OFF_RW1T 8836     // r_w1 transposed: [64 rows][68 stride] (row k = col k of r_w1; [0..63]=feat w, [64..66]=dir w)
#define OFF_RB1  13188    // r_b1 [64]
#define OFF_RW2  13252    // r_w2 [64][3]
#define OFF_RB2  13444    // r_b2 [3]
#define SMEM_FLOATS 13448
#define SMEM_BYTES  (SMEM_FLOATS * 4)

__global__ void __launch_bounds__(256) nerf_render_kernel(
    const float* __restrict__ rays_o, const float* __restrict__ rays_d,
    const float* __restrict__ grid,
    const float* __restrict__ f_w1, const float* __restrict__ f_b1,
    const float* __restrict__ f_w2, const float* __restrict__ f_b2,
    const float* __restrict__ s_w,  const float* __restrict__ s_b,
    const float* __restrict__ r_w1, const float* __restrict__ r_b1,
    const float* __restrict__ r_w2, const float* __restrict__ r_b2,
    float* __restrict__ out)
{
    extern __shared__ float sm[];
    __shared__ float wsum[8];
    __shared__ float wred[8][3];

    const int tid = threadIdx.x;   // sample index 0..255
    const int ray = blockIdx.x;

    // ---- cooperative weight staging ----
    for (int i = tid; i < 384;  i += 256) sm[OFF_W1 + i] = f_w1[i];
    for (int i = tid; i < 128;  i += 256) sm[OFF_B1 + i] = f_b1[i];
    for (int i = tid; i < 8192; i += 256) sm[OFF_W2 + i] = f_w2[i];
    if (tid < 64)               sm[OFF_B2 + tid]      = f_b2[tid];
    if (tid >= 64 && tid < 128) sm[OFF_SW + tid - 64] = s_w[tid - 64];
    if (tid == 128)             sm[OFF_SB]            = s_b[0];
    for (int i = tid; i < 67 * 64; i += 256) {
        int j = i >> 6, k = i & 63;             // r_w1[j][k]
        sm[OFF_RW1T + k * 68 + j] = r_w1[i];    // -> row k, slot j
    }
    if (tid < 64)  sm[OFF_RB1 + tid] = r_b1[tid];
    if (tid < 192) sm[OFF_RW2 + tid] = r_w2[tid];
    if (tid < 3)   sm[OFF_RB2 + tid] = r_b2[tid];
    if (tid < 3)   wred[7][tid] = 0.0f;  // unused slot safety
    __syncthreads();

    // ---- t / dist (unbounded stepping, NEAR=0, range=1, n=256) ----
    const float ustep = (257.0f / 258.0f) / 256.0f;
    float u0 = (float)tid * ustep;
    float u1 = (float)(tid + 1) * ustep;
    float t  = (u0 < 0.5f) ? 2.0f * u0 : 1.0f / (2.0f - 2.0f * u0);
    float t1 = (u1 < 0.5f) ? 2.0f * u1 : 1.0f / (2.0f - 2.0f * u1);
    float dist = t1 - t;

    // ---- sample position + mip360 contraction ----
    const float ox = __ldg(&rays_o[ray * 3 + 0]);
    const float oy = __ldg(&rays_o[ray * 3 + 1]);
    const float oz = __ldg(&rays_o[ray * 3 + 2]);
    const float dx = __ldg(&rays_d[ray * 3 + 0]);
    const float dy = __ldg(&rays_d[ray * 3 + 1]);
    const float dz = __ldg(&rays_d[ray * 3 + 2]);

    float px = ox + dx * t, py = oy + dy * t, pz = oz + dz * t;
    {
        float nrm = sqrtf(px * px + py * py + pz * pz);
        float cs = (nrm <= 1.0f) ? 0.5f : (2.0f - 1.0f / nrm) / nrm * 0.5f;
        px *= cs; py *= cs; pz *= cs;
    }

    // ---- trilinear grid sample (align_corners=False, zeros padding) ----
    float occ = 0.0f;
    {
        float ixf = ((px + 1.0f) * 128.0f - 1.0f) * 0.5f;
        float iyf = ((py + 1.0f) * 128.0f - 1.0f) * 0.5f;
        float izf = ((pz + 1.0f) * 128.0f - 1.0f) * 0.5f;
        float fx0 = floorf(ixf), fy0 = floorf(iyf), fz0 = floorf(izf);
        int ix0 = (int)fx0, iy0 = (int)fy0, iz0 = (int)fz0;
        float fx = ixf - fx0, fy = iyf - fy0, fz = izf - fz0;
        #pragma unroll
        for (int dzc = 0; dzc < 2; dzc++) {
            int cz = iz0 + dzc;
            if (cz < 0 || cz >= 128) continue;
            float wz = dzc ? fz : 1.0f - fz;
            #pragma unroll
            for (int dyc = 0; dyc < 2; dyc++) {
                int cy = iy0 + dyc;
                if (cy < 0 || cy >= 128) continue;
                float wy = dyc ? fy : 1.0f - fy;
                #pragma unroll
                for (int dxc = 0; dxc < 2; dxc++) {
                    int cx = ix0 + dxc;
                    if (cx < 0 || cx >= 128) continue;
                    float wx = dxc ? fx : 1.0f - fx;
                    occ += wz * wy * wx * __ldg(&grid[(cz << 14) + (cy << 7) + cx]);
                }
            }
        }
    }
    const bool mask = occ > OPACITY_TH;

    // ---- feature MLP: relu(p@W1+b1)@W2+b2 ; sigma = softplus(feat@s_w+s_b) ----
    float feat[64];
    #pragma unroll
    for (int j = 0; j < 64; j++) feat[j] = sm[OFF_B2 + j];
    float sigma = 0.0f;
    if (mask) {
        #pragma unroll 4
        for (int k = 0; k < 128; k++) {
            float h = sm[OFF_B1 + k] + px * sm[OFF_W1 + k]
                                     + py * sm[OFF_W1 + 128 + k]
                                     + pz * sm[OFF_W1 + 256 + k];
            h = fmaxf(h, 0.0f);
            const float4* w2r = (const float4*)&sm[OFF_W2 + k * 64];
            #pragma unroll
            for (int j = 0; j < 16; j++) {
                float4 w = w2r[j];
                feat[4 * j + 0] = fmaf(h, w.x, feat[4 * j + 0]);
                feat[4 * j + 1] = fmaf(h, w.y, feat[4 * j + 1]);
                feat[4 * j + 2] = fmaf(h, w.z, feat[4 * j + 2]);
                feat[4 * j + 3] = fmaf(h, w.w, feat[4 * j + 3]);
            }
        }
        float sacc = sm[OFF_SB];
        #pragma unroll
        for (int j = 0; j < 64; j++) sacc = fmaf(feat[j], sm[OFF_SW + j], sacc);
        sigma = (sacc > 20.0f) ? sacc : log1pf(expf(sacc));
    }

    // ---- block-wide exclusive scan of a = -sigma*dist -> trans ----
    float a = -sigma * dist;
    float inc = a;
    #pragma unroll
    for (int off = 1; off < 32; off <<= 1) {
        float y = __shfl_up_sync(0xffffffffu, inc, off);
        if ((tid & 31) >= off) inc += y;
    }
    if ((tid & 31) == 31) wsum[tid >> 5] = inc;
    __syncthreads();
    float woff = 0.0f;
    {
        int w = tid >> 5;
        #pragma unroll
        for (int i = 0; i < 8; i++) if (i < w) woff += wsum[i];
    }
    float excl   = woff + inc - a;
    float trans  = expf(excl);
    float weight = trans * (1.0f - expf(a));
    const bool mask2 = mask && (trans > EARLY_TERM);

    // ---- RGB MLP: relu([feat,dir]@r_w1+r_b1)@r_w2+r_b2 -> sigmoid -> *weight ----
    float r0 = 0.0f, r1 = 0.0f, r2 = 0.0f;
    if (mask2) {
        float a0 = 0.0f, a1 = 0.0f, a2 = 0.0f;
        #pragma unroll 2
        for (int k = 0; k < 64; k++) {
            const float* row = &sm[OFF_RW1T + k * 68];
            const float4* rowv = (const float4*)row;
            float h = sm[OFF_RB1 + k];
            #pragma unroll
            for (int j = 0; j < 16; j++) {
                float4 w = rowv[j];
                h = fmaf(feat[4 * j + 0], w.x, h);
                h = fmaf(feat[4 * j + 1], w.y, h);
                h = fmaf(feat[4 * j + 2], w.z, h);
                h = fmaf(feat[4 * j + 3], w.w, h);
            }
            h = fmaf(dx, row[64], h);
            h = fmaf(dy, row[65], h);
            h = fmaf(dz, row[66], h);
            h = fmaxf(h, 0.0f);
            a0 = fmaf(h, sm[OFF_RW2 + k * 3 + 0], a0);
            a1 = fmaf(h, sm[OFF_RW2 + k * 3 + 1], a1);
            a2 = fmaf(h, sm[OFF_RW2 + k * 3 + 2], a2);
        }
        r0 = weight / (1.0f + expf(-(a0 + sm[OFF_RB2 + 0])));
        r1 = weight / (1.0f + expf(-(a1 + sm[OFF_RB2 + 1])));
        r2 = weight / (1.0f + expf(-(a2 + sm[OFF_RB2 + 2])));
    }

    // ---- deterministic block reduction ----
    #pragma unroll
    for (int off = 16; off > 0; off >>= 1) {
        r0 += __shfl_down_sync(0xffffffffu, r0, off);
        r1 += __shfl_down_sync(0xffffffffu, r1, off);
        r2 += __shfl_down_sync(0xffffffffu, r2, off);
    }
    if ((tid & 31) == 0) {
        wred[tid >> 5][0] = r0;
        wred[tid >> 5][1] = r1;
        wred[tid >> 5][2] = r2;
    }
    __syncthreads();
    if (tid < 3) {
        float s = 0.0f;
        #pragma unroll
        for (int w = 0; w < 8; w++) s += wred[w][tid];
        out[ray * 3 + tid] = s;
    }
}

extern "C" void kernel_launch(void* const* d_in, const int* in_sizes, int n_in,
                              void* d_out, int out_size) {
    const float* rays_o = (const float*)d_in[0];
    const float* rays_d = (const float*)d_in[1];
    const float* grid   = (const float*)d_in[2];
    const float* f_w1   = (const float*)d_in[3];
    const float* f_b1   = (const float*)d_in[4];
    const float* f_w2   = (const float*)d_in[5];
    const float* f_b2   = (const float*)d_in[6];
    const float* s_w    = (const float*)d_in[7];
    const float* s_b    = (const float*)d_in[8];
    const float* r_w1   = (const float*)d_in[9];
    const float* r_b1   = (const float*)d_in[10];
    const float* r_w2   = (const float*)d_in[11];
    const float* r_b2   = (const float*)d_in[12];
    float* out = (float*)d_out;

    const int n_rays = in_sizes[0] / 3;

    cudaFuncSetAttribute(nerf_render_kernel,
                         cudaFuncAttributeMaxDynamicSharedMemorySize, SMEM_BYTES);
    nerf_render_kernel<<<n_rays, 256, SMEM_BYTES>>>(
        rays_o, rays_d, grid, f_w1, f_b1, f_w2, f_b2,
        s_w, s_b, r_w1, r_b1, r_w2, r_b2, out);
}

// round 2
// speedup vs baseline: 1.2836x; 1.2836x over previous
#include <cuda_runtime.h>
#include <math.h>

#define OPACITY_TH 0.01f
#define EARLY_TERM 1e-4f

typedef unsigned long long u64;

__device__ __forceinline__ u64 pack2(float lo, float hi) {
    u64 r; asm("mov.b64 %0, {%1, %2};" : "=l"(r) : "f"(lo), "f"(hi)); return r;
}
__device__ __forceinline__ void unpack2(u64 v, float& a, float& b) {
    asm("mov.b64 {%0, %1}, %2;" : "=f"(a), "=f"(b) : "l"(v));
}
__device__ __forceinline__ u64 fma2(u64 a, u64 b, u64 c) {
    u64 d; asm("fma.rn.f32x2 %0, %1, %2, %3;" : "=l"(d) : "l"(a), "l"(b), "l"(c)); return d;
}

// shared-memory float offsets
#define OFF_W1B  0        // [128][4]: (w1x, w1y, w1z, b1) per hidden unit
#define OFF_W2   512      // f_w2 [128][64]
#define OFF_B2   8704     // f_b2 [64]
#define OFF_SW   8768     // s_w [64]
#define OFF_SB   8832     // s_b (+3 pad)
#define OFF_RW1T 8836     // r_w1^T: [64 rows][68] ([0..63] feat w, [64..66] dir w, [67] pad)
#define OFF_RB1  13188    // r_b1 [64]
#define OFF_RW2  13252    // r_w2 [64][3]
#define OFF_RB2  13444    // r_b2 [3] (+1 pad)
#define SMEM_FLOATS 13448
#define SMEM_BYTES  (SMEM_FLOATS * 4)

__device__ __forceinline__ float sample_grid(const float* __restrict__ grid,
                                             float px, float py, float pz) {
    float ixf = ((px + 1.0f) * 128.0f - 1.0f) * 0.5f;
    float iyf = ((py + 1.0f) * 128.0f - 1.0f) * 0.5f;
    float izf = ((pz + 1.0f) * 128.0f - 1.0f) * 0.5f;
    float fx0 = floorf(ixf), fy0 = floorf(iyf), fz0 = floorf(izf);
    int ix0 = (int)fx0, iy0 = (int)fy0, iz0 = (int)fz0;
    float fx = ixf - fx0, fy = iyf - fy0, fz = izf - fz0;
    float occ = 0.0f;
    #pragma unroll
    for (int dzc = 0; dzc < 2; dzc++) {
        int cz = iz0 + dzc;
        if (cz < 0 || cz >= 128) continue;
        float wz = dzc ? fz : 1.0f - fz;
        #pragma unroll
        for (int dyc = 0; dyc < 2; dyc++) {
            int cy = iy0 + dyc;
            if (cy < 0 || cy >= 128) continue;
            float wy = dyc ? fy : 1.0f - fy;
            #pragma unroll
            for (int dxc = 0; dxc < 2; dxc++) {
                int cx = ix0 + dxc;
                if (cx < 0 || cx >= 128) continue;
                float wx = dxc ? fx : 1.0f - fx;
                occ += wz * wy * wx * __ldg(&grid[(cz << 14) + (cy << 7) + cx]);
            }
        }
    }
    return occ;
}

__device__ __forceinline__ float tmap(float u) {
    return (u < 0.5f) ? 2.0f * u : 1.0f / (2.0f - 2.0f * u);
}

__global__ void __launch_bounds__(128) nerf_render_kernel(
    const float* __restrict__ rays_o, const float* __restrict__ rays_d,
    const float* __restrict__ grid,
    const float* __restrict__ f_w1, const float* __restrict__ f_b1,
    const float* __restrict__ f_w2, const float* __restrict__ f_b2,
    const float* __restrict__ s_w,  const float* __restrict__ s_b,
    const float* __restrict__ r_w1, const float* __restrict__ r_b1,
    const float* __restrict__ r_w2, const float* __restrict__ r_b2,
    float* __restrict__ out)
{
    extern __shared__ float sm[];
    __shared__ float wsum[4];
    __shared__ float wred[4][3];

    const int tid = threadIdx.x;   // thread handles samples 2*tid, 2*tid+1
    const int ray = blockIdx.x;

    // ---- cooperative weight staging (128 threads) ----
    for (int i = tid; i < 512; i += 128) {
        int k = i >> 2, c = i & 3;
        sm[OFF_W1B + i] = (c < 3) ? f_w1[c * 128 + k] : f_b1[k];
    }
    for (int i = tid; i < 8192; i += 128) sm[OFF_W2 + i] = f_w2[i];
    if (tid < 64)                sm[OFF_B2 + tid]      = f_b2[tid];
    if (tid >= 64 && tid < 128)  sm[OFF_SW + tid - 64] = s_w[tid - 64];
    if (tid == 0)                sm[OFF_SB]            = s_b[0];
    for (int i = tid; i < 67 * 64; i += 128) {
        int j = i >> 6, k = i & 63;          // r_w1[j][k]
        sm[OFF_RW1T + k * 68 + j] = r_w1[i]; // -> row k, slot j
    }
    if (tid < 64) { sm[OFF_RW1T + tid * 68 + 67] = 0.0f; }  // pad
    if (tid < 64)  sm[OFF_RB1 + tid] = r_b1[tid];
    for (int i = tid; i < 192; i += 128) sm[OFF_RW2 + i] = r_w2[i];
    if (tid < 3)   sm[OFF_RB2 + tid] = r_b2[tid];
    __syncthreads();

    // ---- t / dist for samples s0=2t, s1=2t+1 ----
    const float ustep = (257.0f / 258.0f) / 256.0f;
    float ua = (float)(2 * tid)     * ustep;
    float ub = (float)(2 * tid + 1) * ustep;
    float uc = (float)(2 * tid + 2) * ustep;
    float t0 = tmap(ua), t1 = tmap(ub), t2 = tmap(uc);
    float dist0 = t1 - t0, dist1 = t2 - t1;

    // ---- positions + mip360 contraction ----
    const float ox = __ldg(&rays_o[ray * 3 + 0]);
    const float oy = __ldg(&rays_o[ray * 3 + 1]);
    const float oz = __ldg(&rays_o[ray * 3 + 2]);
    const float dx = __ldg(&rays_d[ray * 3 + 0]);
    const float dy = __ldg(&rays_d[ray * 3 + 1]);
    const float dz = __ldg(&rays_d[ray * 3 + 2]);

    float px0 = ox + dx * t0, py0 = oy + dy * t0, pz0 = oz + dz * t0;
    float px1 = ox + dx * t1, py1 = oy + dy * t1, pz1 = oz + dz * t1;
    {
        float n0 = sqrtf(px0 * px0 + py0 * py0 + pz0 * pz0);
        float c0 = (n0 <= 1.0f) ? 0.5f : (2.0f - 1.0f / n0) / n0 * 0.5f;
        px0 *= c0; py0 *= c0; pz0 *= c0;
        float n1 = sqrtf(px1 * px1 + py1 * py1 + pz1 * pz1);
        float c1 = (n1 <= 1.0f) ? 0.5f : (2.0f - 1.0f / n1) / n1 * 0.5f;
        px1 *= c1; py1 *= c1; pz1 *= c1;
    }

    // ---- occupancy ----
    float occ0 = sample_grid(grid, px0, py0, pz0);
    float occ1 = sample_grid(grid, px1, py1, pz1);
    const bool m0 = occ0 > OPACITY_TH;
    const bool m1 = occ1 > OPACITY_TH;

    // ---- feature MLP (packed over feature dim, 2 samples share weight loads) ----
    u64 f0[32], f1[32];
    {
        const u64* b2p = (const u64*)&sm[OFF_B2];
        #pragma unroll
        for (int j = 0; j < 32; j++) { u64 b = b2p[j]; f0[j] = b; f1[j] = b; }
    }
    float sigma0 = 0.0f, sigma1 = 0.0f;
    if (m0 || m1) {
        const u64* w2p = (const u64*)&sm[OFF_W2];
        #pragma unroll 2
        for (int k = 0; k < 128; k++) {
            float4 wb = *(const float4*)&sm[OFF_W1B + 4 * k];
            float h0 = wb.w + px0 * wb.x + py0 * wb.y + pz0 * wb.z;
            float h1 = wb.w + px1 * wb.x + py1 * wb.y + pz1 * wb.z;
            h0 = fmaxf(h0, 0.0f);
            h1 = fmaxf(h1, 0.0f);
            u64 hd0 = pack2(h0, h0);
            u64 hd1 = pack2(h1, h1);
            const u64* wr = w2p + (k << 5);
            #pragma unroll
            for (int j = 0; j < 32; j++) {
                u64 w = wr[j];
                f0[j] = fma2(hd0, w, f0[j]);
                f1[j] = fma2(hd1, w, f1[j]);
            }
        }
        // sigma = softplus(feat @ s_w + s_b)
        const u64* swp = (const u64*)&sm[OFF_SW];
        float sb = sm[OFF_SB];
        u64 sa0 = pack2(sb, 0.0f), sa1 = pack2(sb, 0.0f);
        #pragma unroll
        for (int j = 0; j < 32; j++) {
            u64 w = swp[j];
            sa0 = fma2(f0[j], w, sa0);
            sa1 = fma2(f1[j], w, sa1);
        }
        float xa, xb;
        unpack2(sa0, xa, xb); float sacc0 = xa + xb;
        unpack2(sa1, xa, xb); float sacc1 = xa + xb;
        if (m0) sigma0 = (sacc0 > 20.0f) ? sacc0 : log1pf(expf(sacc0));
        if (m1) sigma1 = (sacc1 > 20.0f) ? sacc1 : log1pf(expf(sacc1));
    }

    // ---- block-wide exclusive scan over 256-sample chain (pairs per thread) ----
    float a0 = -sigma0 * dist0;
    float a1 = -sigma1 * dist1;
    float ps = a0 + a1;
    float inc = ps;
    #pragma unroll
    for (int off = 1; off < 32; off <<= 1) {
        float y = __shfl_up_sync(0xffffffffu, inc, off);
        if ((tid & 31) >= off) inc += y;
    }
    if ((tid & 31) == 31) wsum[tid >> 5] = inc;
    __syncthreads();
    float woff = 0.0f;
    {
        int w = tid >> 5;
        #pragma unroll
        for (int i = 0; i < 4; i++) if (i < w) woff += wsum[i];
    }
    float excl0 = woff + inc - ps;           // exclusive prefix at sample 2t
    float excl1 = excl0 + a0;
    float trans0 = expf(excl0), trans1 = expf(excl1);
    float weight0 = trans0 * (1.0f - expf(a0));
    float weight1 = trans1 * (1.0f - expf(a1));
    const bool l0 = m0 && (trans0 > EARLY_TERM);
    const bool l1 = m1 && (trans1 > EARLY_TERM);

    // ---- RGB MLP ----
    float r0 = 0.0f, r1 = 0.0f, r2 = 0.0f;
    if (l0 || l1) {
        float a00 = 0.0f, a01 = 0.0f, a02 = 0.0f;   // sample0 output accum
        float a10 = 0.0f, a11 = 0.0f, a12 = 0.0f;   // sample1 output accum
        #pragma unroll 2
        for (int k = 0; k < 64; k++) {
            const u64* row = (const u64*)&sm[OFF_RW1T + k * 68];
            u64 ha0 = 0ull, hb0 = 0ull, ha1 = 0ull, hb1 = 0ull;
            #pragma unroll
            for (int j = 0; j < 16; j++) {
                u64 wA = row[2 * j], wB = row[2 * j + 1];
                ha0 = fma2(f0[2 * j],     wA, ha0);
                hb0 = fma2(f0[2 * j + 1], wB, hb0);
                ha1 = fma2(f1[2 * j],     wA, ha1);
                hb1 = fma2(f1[2 * j + 1], wB, hb1);
            }
            float4 dw = *(const float4*)&sm[OFF_RW1T + k * 68 + 64];
            float rb = sm[OFF_RB1 + k];
            float base = rb + dx * dw.x + dy * dw.y + dz * dw.z;
            float xa, xb, xc, xd;
            unpack2(ha0, xa, xb); unpack2(hb0, xc, xd);
            float h0 = base + (xa + xb) + (xc + xd);
            unpack2(ha1, xa, xb); unpack2(hb1, xc, xd);
            float h1 = base + (xa + xb) + (xc + xd);
            h0 = fmaxf(h0, 0.0f);
            h1 = fmaxf(h1, 0.0f);
            float w20 = sm[OFF_RW2 + k * 3 + 0];
            float w21 = sm[OFF_RW2 + k * 3 + 1];
            float w22 = sm[OFF_RW2 + k * 3 + 2];
            a00 = fmaf(h0, w20, a00); a01 = fmaf(h0, w21, a01); a02 = fmaf(h0, w22, a02);
            a10 = fmaf(h1, w20, a10); a11 = fmaf(h1, w21, a11); a12 = fmaf(h1, w22, a12);
        }
        float b0 = sm[OFF_RB2 + 0], b1 = sm[OFF_RB2 + 1], b2 = sm[OFF_RB2 + 2];
        if (l0) {
            r0 += weight0 / (1.0f + expf(-(a00 + b0)));
            r1 += weight0 / (1.0f + expf(-(a01 + b1)));
            r2 += weight0 / (1.0f + expf(-(a02 + b2)));
        }
        if (l1) {
            r0 += weight1 / (1.0f + expf(-(a10 + b0)));
            r1 += weight1 / (1.0f + expf(-(a11 + b1)));
            r2 += weight1 / (1.0f + expf(-(a12 + b2)));
        }
    }

    // ---- deterministic block reduction (4 warps) ----
    #pragma unroll
    for (int off = 16; off > 0; off >>= 1) {
        r0 += __shfl_down_sync(0xffffffffu, r0, off);
        r1 += __shfl_down_sync(0xffffffffu, r1, off);
        r2 += __shfl_down_sync(0xffffffffu, r2, off);
    }
    if ((tid & 31) == 0) {
        wred[tid >> 5][0] = r0;
        wred[tid >> 5][1] = r1;
        wred[tid >> 5][2] = r2;
    }
    __syncthreads();
    if (tid < 3) {
        float s = 0.0f;
        #pragma unroll
        for (int w = 0; w < 4; w++) s += wred[w][tid];
        out[ray * 3 + tid] = s;
    }
}

extern "C" void kernel_launch(void* const* d_in, const int* in_sizes, int n_in,
                              void* d_out, int out_size) {
    const float* rays_o = (const float*)d_in[0];
    const float* rays_d = (const float*)d_in[1];
    const float* grid   = (const float*)d_in[2];
    const float* f_w1   = (const float*)d_in[3];
    const float* f_b1   = (const float*)d_in[4];
    const float* f_w2   = (const float*)d_in[5];
    const float* f_b2   = (const float*)d_in[6];
    const float* s_w    = (const float*)d_in[7];
    const float* s_b    = (const float*)d_in[8];
    const float* r_w1   = (const float*)d_in[9];
    const float* r_b1   = (const float*)d_in[10];
    const float* r_w2   = (const float*)d_in[11];
    const float* r_b2   = (const float*)d_in[12];
    float* out = (float*)d_out;

    const int n_rays = in_sizes[0] / 3;

    cudaFuncSetAttribute(nerf_render_kernel,
                         cudaFuncAttributeMaxDynamicSharedMemorySize, SMEM_BYTES);
    nerf_render_kernel<<<n_rays, 128, SMEM_BYTES>>>(
        rays_o, rays_d, grid, f_w1, f_b1, f_w2, f_b2,
        s_w, s_b, r_w1, r_b1, r_w2, r_b2, out);
}

// round 3
// speedup vs baseline: 1.7815x; 1.3878x over previous
#include <cuda_runtime.h>
#include <math.h>

#define OPACITY_TH 0.01f
#define EARLY_TERM 1e-4f

typedef unsigned long long u64;

__device__ __forceinline__ u64 pack2(float lo, float hi) {
    u64 r; asm("mov.b64 %0, {%1, %2};" : "=l"(r) : "f"(lo), "f"(hi)); return r;
}
__device__ __forceinline__ void unpack2(u64 v, float& a, float& b) {
    asm("mov.b64 {%0, %1}, %2;" : "=f"(a), "=f"(b) : "l"(v));
}
__device__ __forceinline__ u64 fma2(u64 a, u64 b, u64 c) {
    u64 d; asm("fma.rn.f32x2 %0, %1, %2, %3;" : "=l"(d) : "l"(a), "l"(b), "l"(c)); return d;
}
__device__ __forceinline__ u64 add2(u64 a, u64 b) {
    u64 d; asm("add.rn.f32x2 %0, %1, %2;" : "=l"(d) : "l"(a), "l"(b)); return d;
}

// ---- precomputed fused weights (device-global scratch; written by prep kernel) ----
__device__ float g_w2r1[128 * 64];   // (f_w2 @ r_w1[:64,:])  [128][64]
__device__ float g_wsdup[128 * 2];   // f_w2[k,:]·s_w, duplicated (pair) per k
__device__ float g_hconst[64];       // f_b2 @ r_w1[:64,:] + r_b1
__device__ float g_sconst[1];        // f_b2·s_w + s_b

__global__ void prep_kernel(const float* __restrict__ f_w2, const float* __restrict__ f_b2,
                            const float* __restrict__ s_w,  const float* __restrict__ s_b,
                            const float* __restrict__ r_w1, const float* __restrict__ r_b1)
{
    int i = blockIdx.x * blockDim.x + threadIdx.x;
    if (i < 8192) {
        int k = i >> 6, j = i & 63;
        float s = 0.0f;
        #pragma unroll 8
        for (int t = 0; t < 64; t++) s += f_w2[k * 64 + t] * r_w1[t * 64 + j];
        g_w2r1[i] = s;
    } else if (i < 8320) {
        int k = i - 8192;
        float s = 0.0f;
        #pragma unroll 8
        for (int t = 0; t < 64; t++) s += f_w2[k * 64 + t] * s_w[t];
        g_wsdup[2 * k] = s; g_wsdup[2 * k + 1] = s;
    } else if (i < 8384) {
        int j = i - 8320;
        float s = r_b1[j];
        #pragma unroll 8
        for (int t = 0; t < 64; t++) s += f_b2[t] * r_w1[t * 64 + j];
        g_hconst[j] = s;
    } else if (i == 8384) {
        float s = s_b[0];
        for (int t = 0; t < 64; t++) s += f_b2[t] * s_w[t];
        g_sconst[0] = s;
    }
}

// shared-memory float offsets
#define OFF_W1B   0       // [128][4]: (w1x, w1y, w1z, b1)
#define OFF_WS    512     // [128][2]: ws duplicated
#define OFF_W2R1  768     // [128][64]
#define OFF_HC    8960    // [64]: per-ray hidden const (g_hconst + dir@r_w1[64:67])
#define OFF_RW2   9024    // [64][4]: r_w2 rows padded
#define OFF_RB2   9280    // [3]
#define OFF_SC    9283    // sconst
#define SMEM_FLOATS 9284
#define SMEM_BYTES  (SMEM_FLOATS * 4)

__device__ __forceinline__ float sample_grid(const float* __restrict__ grid,
                                             float px, float py, float pz) {
    float ixf = ((px + 1.0f) * 128.0f - 1.0f) * 0.5f;
    float iyf = ((py + 1.0f) * 128.0f - 1.0f) * 0.5f;
    float izf = ((pz + 1.0f) * 128.0f - 1.0f) * 0.5f;
    float fx0 = floorf(ixf), fy0 = floorf(iyf), fz0 = floorf(izf);
    int ix0 = (int)fx0, iy0 = (int)fy0, iz0 = (int)fz0;
    float fx = ixf - fx0, fy = iyf - fy0, fz = izf - fz0;
    float occ = 0.0f;
    #pragma unroll
    for (int dzc = 0; dzc < 2; dzc++) {
        int cz = iz0 + dzc;
        if (cz < 0 || cz >= 128) continue;
        float wz = dzc ? fz : 1.0f - fz;
        #pragma unroll
        for (int dyc = 0; dyc < 2; dyc++) {
            int cy = iy0 + dyc;
            if (cy < 0 || cy >= 128) continue;
            float wy = dyc ? fy : 1.0f - fy;
            #pragma unroll
            for (int dxc = 0; dxc < 2; dxc++) {
                int cx = ix0 + dxc;
                if (cx < 0 || cx >= 128) continue;
                float wx = dxc ? fx : 1.0f - fx;
                occ += wz * wy * wx * __ldg(&grid[(cz << 14) + (cy << 7) + cx]);
            }
        }
    }
    return occ;
}

__device__ __forceinline__ float tmap(float u) {
    return (u < 0.5f) ? 2.0f * u : 1.0f / (2.0f - 2.0f * u);
}

__global__ void __launch_bounds__(128) nerf_render_kernel(
    const float* __restrict__ rays_o, const float* __restrict__ rays_d,
    const float* __restrict__ grid,
    const float* __restrict__ f_w1, const float* __restrict__ f_b1,
    const float* __restrict__ r_w1, const float* __restrict__ r_w2,
    const float* __restrict__ r_b2,
    float* __restrict__ out)
{
    extern __shared__ float sm[];
    __shared__ float wsum[4];
    __shared__ float wred[4][3];

    const int tid = threadIdx.x;   // handles samples 2*tid, 2*tid+1
    const int ray = blockIdx.x;

    // ---- per-ray origin/dir (needed before staging hc) ----
    const float ox = __ldg(&rays_o[ray * 3 + 0]);
    const float oy = __ldg(&rays_o[ray * 3 + 1]);
    const float oz = __ldg(&rays_o[ray * 3 + 2]);
    const float dx = __ldg(&rays_d[ray * 3 + 0]);
    const float dy = __ldg(&rays_d[ray * 3 + 1]);
    const float dz = __ldg(&rays_d[ray * 3 + 2]);

    // ---- cooperative weight staging ----
    for (int i = tid; i < 512; i += 128) {
        int k = i >> 2, c = i & 3;
        sm[OFF_W1B + i] = (c < 3) ? f_w1[c * 128 + k] : f_b1[k];
    }
    for (int i = tid; i < 256; i += 128) sm[OFF_WS + i] = g_wsdup[i];
    for (int i = tid; i < 8192; i += 128) sm[OFF_W2R1 + i] = g_w2r1[i];
    if (tid < 64) {
        // hc[j] = g_hconst[j] + dir @ r_w1[64:67, j]
        sm[OFF_HC + tid] = g_hconst[tid]
                         + dx * r_w1[64 * 64 + tid]
                         + dy * r_w1[65 * 64 + tid]
                         + dz * r_w1[66 * 64 + tid];
    }
    for (int i = tid; i < 256; i += 128) {
        int k = i >> 2, c = i & 3;
        sm[OFF_RW2 + i] = (c < 3) ? r_w2[k * 3 + c] : 0.0f;
    }
    if (tid < 3) sm[OFF_RB2 + tid] = r_b2[tid];
    if (tid == 3) sm[OFF_SC] = g_sconst[0];
    __syncthreads();

    // ---- t / dist ----
    const float ustep = (257.0f / 258.0f) / 256.0f;
    float ua = (float)(2 * tid)     * ustep;
    float ub = (float)(2 * tid + 1) * ustep;
    float uc = (float)(2 * tid + 2) * ustep;
    float t0 = tmap(ua), t1 = tmap(ub), t2 = tmap(uc);
    float dist0 = t1 - t0, dist1 = t2 - t1;

    // ---- positions + contraction ----
    float px0 = ox + dx * t0, py0 = oy + dy * t0, pz0 = oz + dz * t0;
    float px1 = ox + dx * t1, py1 = oy + dy * t1, pz1 = oz + dz * t1;
    {
        float n0 = sqrtf(px0 * px0 + py0 * py0 + pz0 * pz0);
        float c0 = (n0 <= 1.0f) ? 0.5f : (2.0f - 1.0f / n0) / n0 * 0.5f;
        px0 *= c0; py0 *= c0; pz0 *= c0;
        float n1 = sqrtf(px1 * px1 + py1 * py1 + pz1 * pz1);
        float c1 = (n1 <= 1.0f) ? 0.5f : (2.0f - 1.0f / n1) / n1 * 0.5f;
        px1 *= c1; py1 *= c1; pz1 *= c1;
    }

    // ---- occupancy ----
    float occ0 = sample_grid(grid, px0, py0, pz0);
    float occ1 = sample_grid(grid, px1, py1, pz1);
    const bool m0 = occ0 > OPACITY_TH;
    const bool m1 = occ1 > OPACITY_TH;

    // ---- fused feature+sigma+rgb1 accumulation ----
    // acc[j] = sum_k relu(h_k) * W2R1[k][j]   (rgb hidden pre-act, minus const)
    // spair  = (sum_k relu(h0_k)*ws, sum_k relu(h1_k)*ws)
    u64 acc0[32], acc1[32];
    #pragma unroll
    for (int j = 0; j < 32; j++) { acc0[j] = 0ull; acc1[j] = 0ull; }
    float sigma0 = 0.0f, sigma1 = 0.0f;
    if (m0 || m1) {
        u64 spair = 0ull;
        const ulonglong2* w2p = (const ulonglong2*)&sm[OFF_W2R1];
        const u64* wsp = (const u64*)&sm[OFF_WS];
        #pragma unroll 2
        for (int k = 0; k < 128; k++) {
            float4 wb = *(const float4*)&sm[OFF_W1B + 4 * k];
            float h0 = fmaxf(wb.w + px0 * wb.x + py0 * wb.y + pz0 * wb.z, 0.0f);
            float h1 = fmaxf(wb.w + px1 * wb.x + py1 * wb.y + pz1 * wb.z, 0.0f);
            spair = fma2(pack2(h0, h1), wsp[k], spair);
            u64 hd0 = pack2(h0, h0);
            u64 hd1 = pack2(h1, h1);
            const ulonglong2* wr = w2p + (k << 4);
            #pragma unroll
            for (int j = 0; j < 16; j++) {
                ulonglong2 w = wr[j];
                acc0[2 * j]     = fma2(hd0, w.x, acc0[2 * j]);
                acc0[2 * j + 1] = fma2(hd0, w.y, acc0[2 * j + 1]);
                acc1[2 * j]     = fma2(hd1, w.x, acc1[2 * j]);
                acc1[2 * j + 1] = fma2(hd1, w.y, acc1[2 * j + 1]);
            }
        }
        float sc = sm[OFF_SC];
        float s0, s1; unpack2(spair, s0, s1);
        s0 += sc; s1 += sc;
        if (m0) sigma0 = (s0 > 20.0f) ? s0 : log1pf(expf(s0));
        if (m1) sigma1 = (s1 > 20.0f) ? s1 : log1pf(expf(s1));
    }

    // ---- block-wide exclusive scan (256-sample chain, pairs per thread) ----
    float a0 = -sigma0 * dist0;
    float a1 = -sigma1 * dist1;
    float ps = a0 + a1;
    float inc = ps;
    #pragma unroll
    for (int off = 1; off < 32; off <<= 1) {
        float y = __shfl_up_sync(0xffffffffu, inc, off);
        if ((tid & 31) >= off) inc += y;
    }
    if ((tid & 31) == 31) wsum[tid >> 5] = inc;
    __syncthreads();
    float woff = 0.0f;
    {
        int w = tid >> 5;
        #pragma unroll
        for (int i = 0; i < 4; i++) if (i < w) woff += wsum[i];
    }
    float excl0 = woff + inc - ps;
    float excl1 = excl0 + a0;
    float trans0 = expf(excl0), trans1 = expf(excl1);
    float weight0 = trans0 * (1.0f - expf(a0));
    float weight1 = trans1 * (1.0f - expf(a1));
    const bool l0 = m0 && (trans0 > EARLY_TERM);
    const bool l1 = m1 && (trans1 > EARLY_TERM);

    // ---- RGB output layer: relu(acc + hc) @ r_w2 ----
    float r0 = 0.0f, r1 = 0.0f, r2 = 0.0f;
    if (l0 || l1) {
        float a00 = 0.0f, a01 = 0.0f, a02 = 0.0f;
        float a10 = 0.0f, a11 = 0.0f, a12 = 0.0f;
        const u64* hcp = (const u64*)&sm[OFF_HC];
        #pragma unroll 4
        for (int j2 = 0; j2 < 32; j2++) {
            u64 hc2 = hcp[j2];
            float xa, xb;
            unpack2(add2(acc0[j2], hc2), xa, xb);
            float h0a = fmaxf(xa, 0.0f), h0b = fmaxf(xb, 0.0f);
            unpack2(add2(acc1[j2], hc2), xa, xb);
            float h1a = fmaxf(xa, 0.0f), h1b = fmaxf(xb, 0.0f);
            float4 wA = *(const float4*)&sm[OFF_RW2 + 8 * j2];
            float4 wB = *(const float4*)&sm[OFF_RW2 + 8 * j2 + 4];
            a00 = fmaf(h0a, wA.x, a00); a01 = fmaf(h0a, wA.y, a01); a02 = fmaf(h0a, wA.z, a02);
            a00 = fmaf(h0b, wB.x, a00); a01 = fmaf(h0b, wB.y, a01); a02 = fmaf(h0b, wB.z, a02);
            a10 = fmaf(h1a, wA.x, a10); a11 = fmaf(h1a, wA.y, a11); a12 = fmaf(h1a, wA.z, a12);
            a10 = fmaf(h1b, wB.x, a10); a11 = fmaf(h1b, wB.y, a11); a12 = fmaf(h1b, wB.z, a12);
        }
        float b0 = sm[OFF_RB2 + 0], b1 = sm[OFF_RB2 + 1], b2 = sm[OFF_RB2 + 2];
        if (l0) {
            r0 += weight0 / (1.0f + expf(-(a00 + b0)));
            r1 += weight0 / (1.0f + expf(-(a01 + b1)));
            r2 += weight0 / (1.0f + expf(-(a02 + b2)));
        }
        if (l1) {
            r0 += weight1 / (1.0f + expf(-(a10 + b0)));
            r1 += weight1 / (1.0f + expf(-(a11 + b1)));
            r2 += weight1 / (1.0f + expf(-(a12 + b2)));
        }
    }

    // ---- deterministic block reduction ----
    #pragma unroll
    for (int off = 16; off > 0; off >>= 1) {
        r0 += __shfl_down_sync(0xffffffffu, r0, off);
        r1 += __shfl_down_sync(0xffffffffu, r1, off);
        r2 += __shfl_down_sync(0xffffffffu, r2, off);
    }
    if ((tid & 31) == 0) {
        wred[tid >> 5][0] = r0;
        wred[tid >> 5][1] = r1;
        wred[tid >> 5][2] = r2;
    }
    __syncthreads();
    if (tid < 3) {
        float s = 0.0f;
        #pragma unroll
        for (int w = 0; w < 4; w++) s += wred[w][tid];
        out[ray * 3 + tid] = s;
    }
}

extern "C" void kernel_launch(void* const* d_in, const int* in_sizes, int n_in,
                              void* d_out, int out_size) {
    const float* rays_o = (const float*)d_in[0];
    const float* rays_d = (const float*)d_in[1];
    const float* grid   = (const float*)d_in[2];
    const float* f_w1   = (const float*)d_in[3];
    const float* f_b1   = (const float*)d_in[4];
    const float* f_w2   = (const float*)d_in[5];
    const float* f_b2   = (const float*)d_in[6];
    const float* s_w    = (const float*)d_in[7];
    const float* s_b    = (const float*)d_in[8];
    const float* r_w1   = (const float*)d_in[9];
    const float* r_b1   = (const float*)d_in[10];
    const float* r_w2   = (const float*)d_in[11];
    const float* r_b2   = (const float*)d_in[12];
    float* out = (float*)d_out;

    const int n_rays = in_sizes[0] / 3;

    prep_kernel<<<(8385 + 255) / 256, 256>>>(f_w2, f_b2, s_w, s_b, r_w1, r_b1);

    cudaFuncSetAttribute(nerf_render_kernel,
                         cudaFuncAttributeMaxDynamicSharedMemorySize, SMEM_BYTES);
    nerf_render_kernel<<<n_rays, 128, SMEM_BYTES>>>(
        rays_o, rays_d, grid, f_w1, f_b1, r_w1, r_w2, r_b2, out);
}

// round 5
// speedup vs baseline: 2.9790x; 1.6722x over previous
#include <cuda_runtime.h>
#include <cuda_bf16.h>
#include <math.h>
#include <stdint.h>

typedef unsigned long long u64;
typedef unsigned int u32;
typedef unsigned short u16;

#define OPACITY_TH 0.01f
#define EARLY_TERM 1e-4f

// pack two floats to bf16x2: low16 = bf16(lo_f), high16 = bf16(hi_f)
__device__ __forceinline__ u32 cvt2(float hi_f, float lo_f) {
    u32 r; asm("cvt.rn.bf16x2.f32 %0, %1, %2;" : "=r"(r) : "f"(hi_f), "f"(lo_f)); return r;
}

__device__ __forceinline__ void mma_bf16(float& d0, float& d1, float& d2, float& d3,
                                         u32 a0, u32 a1, u32 a2, u32 a3,
                                         u32 b0, u32 b1) {
    asm volatile("mma.sync.aligned.m16n8k16.row.col.f32.bf16.bf16.f32 "
        "{%0,%1,%2,%3}, {%4,%5,%6,%7}, {%8,%9}, {%0,%1,%2,%3};"
        : "+f"(d0), "+f"(d1), "+f"(d2), "+f"(d3)
        : "r"(a0), "r"(a1), "r"(a2), "r"(a3), "r"(b0), "r"(b1));
}

// ---------------- precomputed globals (prep kernel output) ----------------
// B fragments for mma m16n8k16 (.col B): for fid = nt*8+kt, lane l:
//   n = nt*8 + (l>>2), t = l&3, k0 = kt*16 + 2t
//   uint4 = { bhi(k0,k0+1), bhi(k0+8,k0+9), blo(k0,k0+1), blo(k0+8,k0+9) }
__device__ __align__(16) uint4 g_Bfrag[64 * 32];
__device__ float g_ws[128];      // f_w2[k,:]·s_w
__device__ float g_hconst[64];   // f_b2 @ r_w1[:64,:] + r_b1
__device__ float g_sconst[1];    // f_b2·s_w + s_b

__global__ void prep_kernel(const float* __restrict__ f_w2, const float* __restrict__ f_b2,
                            const float* __restrict__ s_w,  const float* __restrict__ s_b,
                            const float* __restrict__ r_w1, const float* __restrict__ r_b1)
{
    int i = blockIdx.x * blockDim.x + threadIdx.x;
    if (i < 2048) {
        int fid = i >> 5, lane = i & 31;
        int nt = fid >> 3, kt = fid & 7;
        int n = nt * 8 + (lane >> 2);
        int tq = lane & 3;
        int k0 = kt * 16 + 2 * tq;
        float v[4]; float lo[4];
        #pragma unroll
        for (int e = 0; e < 4; e++) {
            int k = k0 + (e >> 1) * 8 + (e & 1);   // k0, k0+1, k0+8, k0+9
            float s = 0.0f;
            #pragma unroll 8
            for (int t = 0; t < 64; t++) s += f_w2[k * 64 + t] * r_w1[t * 64 + n];
            __nv_bfloat16 bh = __float2bfloat16(s);
            v[e] = s;
            lo[e] = s - __bfloat162float(bh);
        }
        uint4 o;
        o.x = cvt2(v[1], v[0]);
        o.y = cvt2(v[3], v[2]);
        o.z = cvt2(lo[1], lo[0]);
        o.w = cvt2(lo[3], lo[2]);
        g_Bfrag[fid * 32 + lane] = o;
    } else if (i < 2176) {
        int k = i - 2048;
        float s = 0.0f;
        #pragma unroll 8
        for (int t = 0; t < 64; t++) s += f_w2[k * 64 + t] * s_w[t];
        g_ws[k] = s;
    } else if (i < 2240) {
        int j = i - 2176;
        float s = r_b1[j];
        #pragma unroll 8
        for (int t = 0; t < 64; t++) s += f_b2[t] * r_w1[t * 64 + j];
        g_hconst[j] = s;
    } else if (i == 2240) {
        float s = s_b[0];
        for (int t = 0; t < 64; t++) s += f_b2[t] * s_w[t];
        g_sconst[0] = s;
    }
}

// ---------------- dynamic shared layout (bytes) ----------------
#define DSTRIDE  68                     // f32 stride of D rows (pad for banks)
#define SM_BFRAG 0                      // 32KB
#define SM_D     32768                  // 256 * 68 * 4 = 69632
#define SM_W1B   102400                 // [128][4] f32: (w1x,w1y,w1z,b1) 2KB
#define SM_WS    104448                 // ws[128] 512B
#define SM_RW2   104960                 // [64][4]: (rw2_0,rw2_1,rw2_2,hc) 1KB
#define SM_SIG   105984                 // sigma_pre[256] 1KB
#define SM_MISC  107008                 // [0..2]=r_b2, [3]=sconst
#define SMEM_BYTES 107024

__device__ __forceinline__ float tmap(float u) {
    return (u < 0.5f) ? 2.0f * u : 1.0f / (2.0f - 2.0f * u);
}

#define USTEP ((257.0f / 258.0f) / 256.0f)

__device__ __forceinline__ void ray_pos(int s, float ox, float oy, float oz,
                                        float dx, float dy, float dz,
                                        float& px, float& py, float& pz) {
    float tv = tmap((float)s * USTEP);
    px = ox + dx * tv; py = oy + dy * tv; pz = oz + dz * tv;
    float nrm = sqrtf(px * px + py * py + pz * pz);
    float cs = (nrm <= 1.0f) ? 0.5f : (2.0f - 1.0f / nrm) / nrm * 0.5f;
    px *= cs; py *= cs; pz *= cs;
}

__device__ __forceinline__ float sample_grid(const float* __restrict__ grid,
                                             float px, float py, float pz) {
    float ixf = ((px + 1.0f) * 128.0f - 1.0f) * 0.5f;
    float iyf = ((py + 1.0f) * 128.0f - 1.0f) * 0.5f;
    float izf = ((pz + 1.0f) * 128.0f - 1.0f) * 0.5f;
    float fx0 = floorf(ixf), fy0 = floorf(iyf), fz0 = floorf(izf);
    int ix0 = (int)fx0, iy0 = (int)fy0, iz0 = (int)fz0;
    float fx = ixf - fx0, fy = iyf - fy0, fz = izf - fz0;
    float occ = 0.0f;
    #pragma unroll
    for (int dzc = 0; dzc < 2; dzc++) {
        int cz = iz0 + dzc;
        if (cz < 0 || cz >= 128) continue;
        float wz = dzc ? fz : 1.0f - fz;
        #pragma unroll
        for (int dyc = 0; dyc < 2; dyc++) {
            int cy = iy0 + dyc;
            if (cy < 0 || cy >= 128) continue;
            float wy = dyc ? fy : 1.0f - fy;
            #pragma unroll
            for (int dxc = 0; dxc < 2; dxc++) {
                int cx = ix0 + dxc;
                if (cx < 0 || cx >= 128) continue;
                float wx = dxc ? fx : 1.0f - fx;
                occ += wz * wy * wx * __ldg(&grid[(cz << 14) + (cy << 7) + cx]);
            }
        }
    }
    return occ;
}

__global__ void __launch_bounds__(128) nerf_render_kernel(
    const float* __restrict__ rays_o, const float* __restrict__ rays_d,
    const float* __restrict__ grid,
    const float* __restrict__ f_w1, const float* __restrict__ f_b1,
    const float* __restrict__ r_w1, const float* __restrict__ r_w2,
    const float* __restrict__ r_b2,
    float* __restrict__ out)
{
    extern __shared__ __align__(16) char smdyn[];
    __shared__ float wsumA[4], wsumB[4];
    __shared__ float wred[4][3];

    const int tid = threadIdx.x;
    const int wid = tid >> 5;
    const int lid = tid & 31;
    const int g   = lid >> 2;   // mma group id
    const int tq  = lid & 3;    // mma thread-in-group
    const int ray = blockIdx.x;

    const float ox = __ldg(&rays_o[ray * 3 + 0]);
    const float oy = __ldg(&rays_o[ray * 3 + 1]);
    const float oz = __ldg(&rays_o[ray * 3 + 2]);
    const float dx = __ldg(&rays_d[ray * 3 + 0]);
    const float dy = __ldg(&rays_d[ray * 3 + 1]);
    const float dz = __ldg(&rays_d[ray * 3 + 2]);

    // ---- staging ----
    {
        uint4* dstB = (uint4*)(smdyn + SM_BFRAG);
        #pragma unroll
        for (int i = 0; i < 16; i++) dstB[tid + 128 * i] = g_Bfrag[tid + 128 * i];
        float* dw1b = (float*)(smdyn + SM_W1B);
        for (int i = tid; i < 512; i += 128) {
            int k = i >> 2, c = i & 3;
            dw1b[i] = (c < 3) ? f_w1[c * 128 + k] : f_b1[k];
        }
        ((float*)(smdyn + SM_WS))[tid] = g_ws[tid];
        if (tid < 64) {
            float hcv = g_hconst[tid]
                      + dx * r_w1[64 * 64 + tid]
                      + dy * r_w1[65 * 64 + tid]
                      + dz * r_w1[66 * 64 + tid];
            *(float4*)(smdyn + SM_RW2 + tid * 16) =
                make_float4(r_w2[tid * 3], r_w2[tid * 3 + 1], r_w2[tid * 3 + 2], hcv);
        }
        if (tid < 3)  ((float*)(smdyn + SM_MISC))[tid] = r_b2[tid];
        if (tid == 3) ((float*)(smdyn + SM_MISC))[3] = g_sconst[0];
    }
    __syncthreads();

    const float4* w1bv = (const float4*)(smdyn + SM_W1B);
    const float*  wsf  = (const float*)(smdyn + SM_WS);
    const uint4*  bp   = (const uint4*)(smdyn + SM_BFRAG);
    float*        Db   = (float*)(smdyn + SM_D);
    float*        sigp = (float*)(smdyn + SM_SIG);

    // ================= MMA phase: warp w owns sample rows [64w, 64w+64) =====
    #pragma unroll
    for (int mt = 0; mt < 4; mt++) {
        const int r0 = 64 * wid + 16 * mt + g;
        const int r1 = r0 + 8;
        float px0, py0, pz0, px1, py1, pz1;
        ray_pos(r0, ox, oy, oz, dx, dy, dz, px0, py0, pz0);
        ray_pos(r1, ox, oy, oz, dx, dy, dz, px1, py1, pz1);

        u32 ahi[8][4], alo[8][4];
        float sp0 = 0.0f, sp1 = 0.0f;
        #pragma unroll
        for (int kt = 0; kt < 8; kt++) {
            const int k0 = kt * 16 + 2 * tq;
            float4 wa = w1bv[k0],     wb = w1bv[k0 + 1];
            float4 wc = w1bv[k0 + 8], wd = w1bv[k0 + 9];
            float h00 = fmaxf(wa.w + px0 * wa.x + py0 * wa.y + pz0 * wa.z, 0.0f);
            float h01 = fmaxf(wb.w + px0 * wb.x + py0 * wb.y + pz0 * wb.z, 0.0f);
            float h08 = fmaxf(wc.w + px0 * wc.x + py0 * wc.y + pz0 * wc.z, 0.0f);
            float h09 = fmaxf(wd.w + px0 * wd.x + py0 * wd.y + pz0 * wd.z, 0.0f);
            float h10 = fmaxf(wa.w + px1 * wa.x + py1 * wa.y + pz1 * wa.z, 0.0f);
            float h11 = fmaxf(wb.w + px1 * wb.x + py1 * wb.y + pz1 * wb.z, 0.0f);
            float h18 = fmaxf(wc.w + px1 * wc.x + py1 * wc.y + pz1 * wc.z, 0.0f);
            float h19 = fmaxf(wd.w + px1 * wd.x + py1 * wd.y + pz1 * wd.z, 0.0f);
            float2 wsa = *(const float2*)&wsf[k0];
            float2 wsb = *(const float2*)&wsf[k0 + 8];
            sp0 += h00 * wsa.x + h01 * wsa.y + h08 * wsb.x + h09 * wsb.y;
            sp1 += h10 * wsa.x + h11 * wsa.y + h18 * wsb.x + h19 * wsb.y;
            // a0: row g cols k0,k0+1 ; a1: row g+8 ; a2: row g cols +8 ; a3: row g+8 cols +8
            u32 x0 = cvt2(h01, h00);
            u32 x1 = cvt2(h11, h10);
            u32 x2 = cvt2(h09, h08);
            u32 x3 = cvt2(h19, h18);
            ahi[kt][0] = x0; ahi[kt][1] = x1; ahi[kt][2] = x2; ahi[kt][3] = x3;
            float f00 = __uint_as_float(x0 << 16), f01 = __uint_as_float(x0 & 0xFFFF0000u);
            float f10 = __uint_as_float(x1 << 16), f11 = __uint_as_float(x1 & 0xFFFF0000u);
            float f08 = __uint_as_float(x2 << 16), f09 = __uint_as_float(x2 & 0xFFFF0000u);
            float f18 = __uint_as_float(x3 << 16), f19 = __uint_as_float(x3 & 0xFFFF0000u);
            alo[kt][0] = cvt2(h01 - f01, h00 - f00);
            alo[kt][1] = cvt2(h11 - f11, h10 - f10);
            alo[kt][2] = cvt2(h09 - f09, h08 - f08);
            alo[kt][3] = cvt2(h19 - f19, h18 - f18);
        }
        // sigma partial: quad reduce (lanes 4g..4g+3 hold disjoint k subsets)
        sp0 += __shfl_xor_sync(0xffffffffu, sp0, 1);
        sp0 += __shfl_xor_sync(0xffffffffu, sp0, 2);
        sp1 += __shfl_xor_sync(0xffffffffu, sp1, 1);
        sp1 += __shfl_xor_sync(0xffffffffu, sp1, 2);
        if (tq == 0) { sigp[r0] = sp0; sigp[r1] = sp1; }

        // 8 n-tiles x 8 k-tiles x 3 passes
        #pragma unroll
        for (int nt = 0; nt < 8; nt++) {
            float d0 = 0.0f, d1 = 0.0f, d2 = 0.0f, d3 = 0.0f;
            const uint4* bnt = bp + nt * 8 * 32 + lid;
            #pragma unroll
            for (int kt = 0; kt < 8; kt++) {
                uint4 b = bnt[kt * 32];
                mma_bf16(d0, d1, d2, d3, ahi[kt][0], ahi[kt][1], ahi[kt][2], ahi[kt][3], b.x, b.y);
                mma_bf16(d0, d1, d2, d3, ahi[kt][0], ahi[kt][1], ahi[kt][2], ahi[kt][3], b.z, b.w);
                mma_bf16(d0, d1, d2, d3, alo[kt][0], alo[kt][1], alo[kt][2], alo[kt][3], b.x, b.y);
            }
            int c = nt * 8 + 2 * tq;
            *(float2*)(Db + r0 * DSTRIDE + c) = make_float2(d0, d1);
            *(float2*)(Db + r1 * DSTRIDE + c) = make_float2(d2, d3);
        }
    }
    __syncthreads();

    // ================= scan phase: thread t owns samples t, t+128 ===========
    float tA  = tmap((float)tid * USTEP);
    float tA1 = tmap((float)(tid + 1) * USTEP);
    float tB  = tmap((float)(tid + 128) * USTEP);
    float tB1 = tmap((float)(tid + 129) * USTEP);
    float distA = tA1 - tA, distB = tB1 - tB;

    float pxA, pyA, pzA, pxB, pyB, pzB;
    ray_pos(tid, ox, oy, oz, dx, dy, dz, pxA, pyA, pzA);
    ray_pos(tid + 128, ox, oy, oz, dx, dy, dz, pxB, pyB, pzB);
    const bool mA = sample_grid(grid, pxA, pyA, pzA) > OPACITY_TH;
    const bool mB = sample_grid(grid, pxB, pyB, pzB) > OPACITY_TH;

    const float sconst = ((const float*)(smdyn + SM_MISC))[3];
    float preA = sigp[tid] + sconst;
    float preB = sigp[tid + 128] + sconst;
    float sigmaA = mA ? ((preA > 20.0f) ? preA : log1pf(expf(preA))) : 0.0f;
    float sigmaB = mB ? ((preB > 20.0f) ? preB : log1pf(expf(preB))) : 0.0f;

    float aA = -sigmaA * distA;
    float aB = -sigmaB * distB;
    float incA = aA, incB = aB;
    #pragma unroll
    for (int off = 1; off < 32; off <<= 1) {
        float yA = __shfl_up_sync(0xffffffffu, incA, off);
        float yB = __shfl_up_sync(0xffffffffu, incB, off);
        if (lid >= off) { incA += yA; incB += yB; }
    }
    if (lid == 31) { wsumA[wid] = incA; wsumB[wid] = incB; }
    __syncthreads();
    float offA = 0.0f, offB = 0.0f, totalA = 0.0f;
    #pragma unroll
    for (int i = 0; i < 4; i++) {
        float vA = wsumA[i];
        totalA += vA;
        if (i < wid) { offA += vA; offB += wsumB[i]; }
    }
    float exclA = offA + incA - aA;
    float exclB = totalA + offB + incB - aB;
    float transA = expf(exclA), transB = expf(exclB);
    float weightA = transA * (1.0f - expf(aA));
    float weightB = transB * (1.0f - expf(aB));
    const bool lA = mA && (transA > EARLY_TERM);
    const bool lB = mB && (transB > EARLY_TERM);

    // ================= epilogue: rgb = sigmoid(relu(D + hc) @ rw2 + b) * w ==
    const float rb0  = ((const float*)(smdyn + SM_MISC))[0];
    const float rb1  = ((const float*)(smdyn + SM_MISC))[1];
    const float rb2v = ((const float*)(smdyn + SM_MISC))[2];
    const float4* qrw2 = (const float4*)(smdyn + SM_RW2);
    const float* DrA = Db + tid * DSTRIDE;
    const float* DrB = Db + (tid + 128) * DSTRIDE;

    float a00 = 0.0f, a01 = 0.0f, a02 = 0.0f;
    float a10 = 0.0f, a11 = 0.0f, a12 = 0.0f;
    #pragma unroll 4
    for (int j4 = 0; j4 < 16; j4++) {
        float4 dA = *(const float4*)(DrA + 4 * j4);
        float4 dB = *(const float4*)(DrB + 4 * j4);
        #pragma unroll
        for (int e = 0; e < 4; e++) {
            float4 w = qrw2[4 * j4 + e];
            float dva = (e == 0) ? dA.x : (e == 1) ? dA.y : (e == 2) ? dA.z : dA.w;
            float dvb = (e == 0) ? dB.x : (e == 1) ? dB.y : (e == 2) ? dB.z : dB.w;
            float hA = fmaxf(dva + w.w, 0.0f);
            float hB = fmaxf(dvb + w.w, 0.0f);
            a00 = fmaf(hA, w.x, a00); a01 = fmaf(hA, w.y, a01); a02 = fmaf(hA, w.z, a02);
            a10 = fmaf(hB, w.x, a10); a11 = fmaf(hB, w.y, a11); a12 = fmaf(hB, w.z, a12);
        }
    }
    float r0 = 0.0f, r1 = 0.0f, r2 = 0.0f;
    if (lA) {
        r0 += weightA / (1.0f + expf(-(a00 + rb0)));
        r1 += weightA / (1.0f + expf(-(a01 + rb1)));
        r2 += weightA / (1.0f + expf(-(a02 + rb2v)));
    }
    if (lB) {
        r0 += weightB / (1.0f + expf(-(a10 + rb0)));
        r1 += weightB / (1.0f + expf(-(a11 + rb1)));
        r2 += weightB / (1.0f + expf(-(a12 + rb2v)));
    }

    // ---- deterministic block reduction ----
    #pragma unroll
    for (int off = 16; off > 0; off >>= 1) {
        r0 += __shfl_down_sync(0xffffffffu, r0, off);
        r1 += __shfl_down_sync(0xffffffffu, r1, off);
        r2 += __shfl_down_sync(0xffffffffu, r2, off);
    }
    if (lid == 0) { wred[wid][0] = r0; wred[wid][1] = r1; wred[wid][2] = r2; }
    __syncthreads();
    if (tid < 3) {
        float s = 0.0f;
        #pragma unroll
        for (int w = 0; w < 4; w++) s += wred[w][tid];
        out[ray * 3 + tid] = s;
    }
}

extern "C" void kernel_launch(void* const* d_in, const int* in_sizes, int n_in,
                              void* d_out, int out_size) {
    const float* rays_o = (const float*)d_in[0];
    const float* rays_d = (const float*)d_in[1];
    const float* grid   = (const float*)d_in[2];
    const float* f_w1   = (const float*)d_in[3];
    const float* f_b1   = (const float*)d_in[4];
    const float* f_w2   = (const float*)d_in[5];
    const float* f_b2   = (const float*)d_in[6];
    const float* s_w    = (const float*)d_in[7];
    const float* s_b    = (const float*)d_in[8];
    const float* r_w1   = (const float*)d_in[9];
    const float* r_b1   = (const float*)d_in[10];
    const float* r_w2   = (const float*)d_in[11];
    const float* r_b2   = (const float*)d_in[12];
    float* out = (float*)d_out;

    const int n_rays = in_sizes[0] / 3;

    prep_kernel<<<(2241 + 255) / 256, 256>>>(f_w2, f_b2, s_w, s_b, r_w1, r_b1);

    cudaFuncSetAttribute(nerf_render_kernel,
                         cudaFuncAttributeMaxDynamicSharedMemorySize, SMEM_BYTES);
    nerf_render_kernel<<<n_rays, 128, SMEM_BYTES>>>(
        rays_o, rays_d, grid, f_w1, f_b1, r_w1, r_w2, r_b2, out);
}

// round 6
// speedup vs baseline: 3.7973x; 1.2747x over previous
#include <cuda_runtime.h>
#include <cuda_bf16.h>
#include <math.h>

typedef unsigned int u32;

#define OPACITY_TH 0.01f
#define EARLY_TERM 1e-4f

// pack two floats to bf16x2: low16 = bf16(lo_f), high16 = bf16(hi_f)
__device__ __forceinline__ u32 cvt2(float hi_f, float lo_f) {
    u32 r; asm("cvt.rn.bf16x2.f32 %0, %1, %2;" : "=r"(r) : "f"(hi_f), "f"(lo_f)); return r;
}

__device__ __forceinline__ void mma_bf16(float& d0, float& d1, float& d2, float& d3,
                                         u32 a0, u32 a1, u32 a2, u32 a3,
                                         u32 b0, u32 b1) {
    asm volatile("mma.sync.aligned.m16n8k16.row.col.f32.bf16.bf16.f32 "
        "{%0,%1,%2,%3}, {%4,%5,%6,%7}, {%8,%9}, {%0,%1,%2,%3};"
        : "+f"(d0), "+f"(d1), "+f"(d2), "+f"(d3)
        : "r"(a0), "r"(a1), "r"(a2), "r"(a3), "r"(b0), "r"(b1));
}

// ---------------- precomputed globals (prep kernel output) ----------------
// B fragments for mma m16n8k16 (.col B): fid = nt*8+kt, lane l:
//   n = nt*8 + (l>>2), t = l&3, k0 = kt*16 + 2t
//   uint4 = { bhi(k0,k0+1), bhi(k0+8,k0+9), blo(k0,k0+1), blo(k0+8,k0+9) }
__device__ __align__(16) uint4 g_Bfrag[64 * 32];
__device__ float g_ws[128];      // f_w2[k,:]·s_w
__device__ float g_hconst[64];   // f_b2 @ r_w1[:64,:] + r_b1
__device__ float g_sconst[1];    // f_b2·s_w + s_b

__global__ void prep_kernel(const float* __restrict__ f_w2, const float* __restrict__ f_b2,
                            const float* __restrict__ s_w,  const float* __restrict__ s_b,
                            const float* __restrict__ r_w1, const float* __restrict__ r_b1)
{
    int i = blockIdx.x * blockDim.x + threadIdx.x;
    if (i < 2048) {
        int fid = i >> 5, lane = i & 31;
        int nt = fid >> 3, kt = fid & 7;
        int n = nt * 8 + (lane >> 2);
        int tq = lane & 3;
        int k0 = kt * 16 + 2 * tq;
        float v[4]; float lo[4];
        #pragma unroll
        for (int e = 0; e < 4; e++) {
            int k = k0 + (e >> 1) * 8 + (e & 1);   // k0, k0+1, k0+8, k0+9
            float s = 0.0f;
            #pragma unroll 8
            for (int t = 0; t < 64; t++) s += f_w2[k * 64 + t] * r_w1[t * 64 + n];
            __nv_bfloat16 bh = __float2bfloat16(s);
            v[e] = s;
            lo[e] = s - __bfloat162float(bh);
        }
        uint4 o;
        o.x = cvt2(v[1], v[0]);
        o.y = cvt2(v[3], v[2]);
        o.z = cvt2(lo[1], lo[0]);
        o.w = cvt2(lo[3], lo[2]);
        g_Bfrag[fid * 32 + lane] = o;
    } else if (i < 2176) {
        int k = i - 2048;
        float s = 0.0f;
        #pragma unroll 8
        for (int t = 0; t < 64; t++) s += f_w2[k * 64 + t] * s_w[t];
        g_ws[k] = s;
    } else if (i < 2240) {
        int j = i - 2176;
        float s = r_b1[j];
        #pragma unroll 8
        for (int t = 0; t < 64; t++) s += f_b2[t] * r_w1[t * 64 + j];
        g_hconst[j] = s;
    } else if (i == 2240) {
        float s = s_b[0];
        for (int t = 0; t < 64; t++) s += f_b2[t] * s_w[t];
        g_sconst[0] = s;
    }
}

// ---------------- dynamic shared layout (bytes) ----------------
#define SM_BFRAG 0        // 32KB uint4[2048]
#define SM_W1B   32768    // [128][4] f32: (w1x,w1y,w1z,b1)  2KB
#define SM_WS    34816    // ws[128] f32                     512B
#define SM_RW2   35328    // [64][4]: (rw2_0,rw2_1,rw2_2,hc) 1KB
#define SM_WBUF  36352    // weight[256] (0 if !mask2)       1KB
#define SM_MISC  37376    // [0..2]=r_b2 (+pad)
#define SMEM_BYTES 37392

__device__ __forceinline__ float tmap(float u) {
    return (u < 0.5f) ? 2.0f * u : 1.0f / (2.0f - 2.0f * u);
}

#define USTEP ((257.0f / 258.0f) / 256.0f)

__device__ __forceinline__ void ray_pos(int s, float ox, float oy, float oz,
                                        float dx, float dy, float dz,
                                        float& px, float& py, float& pz) {
    float tv = tmap((float)s * USTEP);
    px = ox + dx * tv; py = oy + dy * tv; pz = oz + dz * tv;
    float nrm = sqrtf(px * px + py * py + pz * pz);
    float cs = (nrm <= 1.0f) ? 0.5f : (2.0f - 1.0f / nrm) / nrm * 0.5f;
    px *= cs; py *= cs; pz *= cs;
}

__device__ __forceinline__ float sample_grid(const float* __restrict__ grid,
                                             float px, float py, float pz) {
    float ixf = ((px + 1.0f) * 128.0f - 1.0f) * 0.5f;
    float iyf = ((py + 1.0f) * 128.0f - 1.0f) * 0.5f;
    float izf = ((pz + 1.0f) * 128.0f - 1.0f) * 0.5f;
    float fx0 = floorf(ixf), fy0 = floorf(iyf), fz0 = floorf(izf);
    int ix0 = (int)fx0, iy0 = (int)fy0, iz0 = (int)fz0;
    float fx = ixf - fx0, fy = iyf - fy0, fz = izf - fz0;
    float occ = 0.0f;
    #pragma unroll
    for (int dzc = 0; dzc < 2; dzc++) {
        int cz = iz0 + dzc;
        if (cz < 0 || cz >= 128) continue;
        float wz = dzc ? fz : 1.0f - fz;
        #pragma unroll
        for (int dyc = 0; dyc < 2; dyc++) {
            int cy = iy0 + dyc;
            if (cy < 0 || cy >= 128) continue;
            float wy = dyc ? fy : 1.0f - fy;
            #pragma unroll
            for (int dxc = 0; dxc < 2; dxc++) {
                int cx = ix0 + dxc;
                if (cx < 0 || cx >= 128) continue;
                float wx = dxc ? fx : 1.0f - fx;
                occ += wz * wy * wx * __ldg(&grid[(cz << 14) + (cy << 7) + cx]);
            }
        }
    }
    return occ;
}

__global__ void __launch_bounds__(128, 4) nerf_render_kernel(
    const float* __restrict__ rays_o, const float* __restrict__ rays_d,
    const float* __restrict__ grid,
    const float* __restrict__ f_w1, const float* __restrict__ f_b1,
    const float* __restrict__ r_w1, const float* __restrict__ r_w2,
    const float* __restrict__ r_b2,
    float* __restrict__ out)
{
    extern __shared__ __align__(16) char smdyn[];
    __shared__ float wsumA[4], wsumB[4];
    __shared__ float wred[4][3];

    const int tid = threadIdx.x;
    const int wid = tid >> 5;
    const int lid = tid & 31;
    const int g   = lid >> 2;   // mma group id (row within tile)
    const int tq  = lid & 3;    // mma thread-in-group (col pair)
    const int ray = blockIdx.x;

    const float ox = __ldg(&rays_o[ray * 3 + 0]);
    const float oy = __ldg(&rays_o[ray * 3 + 1]);
    const float oz = __ldg(&rays_o[ray * 3 + 2]);
    const float dx = __ldg(&rays_d[ray * 3 + 0]);
    const float dy = __ldg(&rays_d[ray * 3 + 1]);
    const float dz = __ldg(&rays_d[ray * 3 + 2]);

    // ---- staging ----
    {
        uint4* dstB = (uint4*)(smdyn + SM_BFRAG);
        #pragma unroll
        for (int i = 0; i < 16; i++) dstB[tid + 128 * i] = g_Bfrag[tid + 128 * i];
        float* dw1b = (float*)(smdyn + SM_W1B);
        for (int i = tid; i < 512; i += 128) {
            int k = i >> 2, c = i & 3;
            dw1b[i] = (c < 3) ? f_w1[c * 128 + k] : f_b1[k];
        }
        ((float*)(smdyn + SM_WS))[tid] = g_ws[tid];
        if (tid < 64) {
            float hcv = g_hconst[tid]
                      + dx * r_w1[64 * 64 + tid]
                      + dy * r_w1[65 * 64 + tid]
                      + dz * r_w1[66 * 64 + tid];
            *(float4*)(smdyn + SM_RW2 + tid * 16) =
                make_float4(r_w2[tid * 3], r_w2[tid * 3 + 1], r_w2[tid * 3 + 2], hcv);
        }
        if (tid < 3) ((float*)(smdyn + SM_MISC))[tid] = r_b2[tid];
    }
    __syncthreads();

    const float4* w1bv = (const float4*)(smdyn + SM_W1B);
    const float*  wsf  = (const float*)(smdyn + SM_WS);
    const uint4*  bp   = (const uint4*)(smdyn + SM_BFRAG);
    const float4* qrw2 = (const float4*)(smdyn + SM_RW2);
    float*        wbuf = (float*)(smdyn + SM_WBUF);
    const float sconst = g_sconst[0];

    // ========== PHASE 1: sigma + scan + weights (thread t ~ samples t, t+128)
    {
        float tA  = tmap((float)tid * USTEP);
        float tA1 = tmap((float)(tid + 1) * USTEP);
        float tB  = tmap((float)(tid + 128) * USTEP);
        float tB1 = tmap((float)(tid + 129) * USTEP);
        float distA = tA1 - tA, distB = tB1 - tB;

        float pxA, pyA, pzA, pxB, pyB, pzB;
        ray_pos(tid, ox, oy, oz, dx, dy, dz, pxA, pyA, pzA);
        ray_pos(tid + 128, ox, oy, oz, dx, dy, dz, pxB, pyB, pzB);
        const bool mA = sample_grid(grid, pxA, pyA, pzA) > OPACITY_TH;
        const bool mB = sample_grid(grid, pxB, pyB, pzB) > OPACITY_TH;

        float preA = sconst, preB = sconst;
        if (mA || mB) {
            #pragma unroll 4
            for (int k = 0; k < 128; k++) {
                float4 w = w1bv[k];
                float ws = wsf[k];
                float hA = fmaxf(w.w + pxA * w.x + pyA * w.y + pzA * w.z, 0.0f);
                float hB = fmaxf(w.w + pxB * w.x + pyB * w.y + pzB * w.z, 0.0f);
                preA = fmaf(hA, ws, preA);
                preB = fmaf(hB, ws, preB);
            }
        }
        float sigmaA = mA ? ((preA > 20.0f) ? preA : log1pf(expf(preA))) : 0.0f;
        float sigmaB = mB ? ((preB > 20.0f) ? preB : log1pf(expf(preB))) : 0.0f;

        float aA = -sigmaA * distA;
        float aB = -sigmaB * distB;
        float incA = aA, incB = aB;
        #pragma unroll
        for (int off = 1; off < 32; off <<= 1) {
            float yA = __shfl_up_sync(0xffffffffu, incA, off);
            float yB = __shfl_up_sync(0xffffffffu, incB, off);
            if (lid >= off) { incA += yA; incB += yB; }
        }
        if (lid == 31) { wsumA[wid] = incA; wsumB[wid] = incB; }
        __syncthreads();
        float offA = 0.0f, offB = 0.0f, totalA = 0.0f;
        #pragma unroll
        for (int i = 0; i < 4; i++) {
            float vA = wsumA[i];
            totalA += vA;
            if (i < wid) { offA += vA; offB += wsumB[i]; }
        }
        float exclA = offA + incA - aA;
        float exclB = totalA + offB + incB - aB;
        float transA = expf(exclA), transB = expf(exclB);
        float weightA = transA * (1.0f - expf(aA));
        float weightB = transB * (1.0f - expf(aB));
        wbuf[tid]       = (mA && transA > EARLY_TERM) ? weightA : 0.0f;
        wbuf[tid + 128] = (mB && transB > EARLY_TERM) ? weightB : 0.0f;
    }
    __syncthreads();

    // ========== PHASE 2: gated MMA + in-register epilogue ====================
    // warp wid owns sample rows [64*wid, 64*wid+64); mt tile rows r0=64w+16mt+g, r1=r0+8
    float rgb0 = 0.0f, rgb1 = 0.0f, rgb2 = 0.0f;

    #pragma unroll
    for (int mt = 0; mt < 4; mt++) {
        const int r0 = 64 * wid + 16 * mt + g;
        const int r1 = r0 + 8;
        const float w0 = wbuf[r0];
        const float w1 = wbuf[r1];
        // skip whole 16-row tile if every weight is exactly zero (output identical)
        if (!__any_sync(0xffffffffu, (w0 != 0.0f) | (w1 != 0.0f))) continue;

        float px0, py0, pz0, px1, py1, pz1;
        ray_pos(r0, ox, oy, oz, dx, dy, dz, px0, py0, pz0);
        ray_pos(r1, ox, oy, oz, dx, dy, dz, px1, py1, pz1);

        // A fragments (hi + lo bf16 split)
        u32 ahi[8][4], alo[8][4];
        #pragma unroll
        for (int kt = 0; kt < 8; kt++) {
            const int k0 = kt * 16 + 2 * tq;
            float4 wa = w1bv[k0],     wb = w1bv[k0 + 1];
            float4 wc = w1bv[k0 + 8], wd = w1bv[k0 + 9];
            float h00 = fmaxf(wa.w + px0 * wa.x + py0 * wa.y + pz0 * wa.z, 0.0f);
            float h01 = fmaxf(wb.w + px0 * wb.x + py0 * wb.y + pz0 * wb.z, 0.0f);
            float h08 = fmaxf(wc.w + px0 * wc.x + py0 * wc.y + pz0 * wc.z, 0.0f);
            float h09 = fmaxf(wd.w + px0 * wd.x + py0 * wd.y + pz0 * wd.z, 0.0f);
            float h10 = fmaxf(wa.w + px1 * wa.x + py1 * wa.y + pz1 * wa.z, 0.0f);
            float h11 = fmaxf(wb.w + px1 * wb.x + py1 * wb.y + pz1 * wb.z, 0.0f);
            float h18 = fmaxf(wc.w + px1 * wc.x + py1 * wc.y + pz1 * wc.z, 0.0f);
            float h19 = fmaxf(wd.w + px1 * wd.x + py1 * wd.y + pz1 * wd.z, 0.0f);
            u32 x0 = cvt2(h01, h00);
            u32 x1 = cvt2(h11, h10);
            u32 x2 = cvt2(h09, h08);
            u32 x3 = cvt2(h19, h18);
            ahi[kt][0] = x0; ahi[kt][1] = x1; ahi[kt][2] = x2; ahi[kt][3] = x3;
            float f00 = __uint_as_float(x0 << 16), f01 = __uint_as_float(x0 & 0xFFFF0000u);
            float f10 = __uint_as_float(x1 << 16), f11 = __uint_as_float(x1 & 0xFFFF0000u);
            float f08 = __uint_as_float(x2 << 16), f09 = __uint_as_float(x2 & 0xFFFF0000u);
            float f18 = __uint_as_float(x3 << 16), f19 = __uint_as_float(x3 & 0xFFFF0000u);
            alo[kt][0] = cvt2(h01 - f01, h00 - f00);
            alo[kt][1] = cvt2(h11 - f11, h10 - f10);
            alo[kt][2] = cvt2(h09 - f09, h08 - f08);
            alo[kt][3] = cvt2(h19 - f19, h18 - f18);
        }

        float a00 = 0.0f, a01 = 0.0f, a02 = 0.0f;   // row r0 rgb pre-act
        float a10 = 0.0f, a11 = 0.0f, a12 = 0.0f;   // row r1
        #pragma unroll
        for (int nt = 0; nt < 8; nt++) {
            // three independent accumulator sets (short chains)
            float p0 = 0.0f, p1 = 0.0f, p2 = 0.0f, p3 = 0.0f;   // hi*hi
            float q0 = 0.0f, q1 = 0.0f, q2 = 0.0f, q3 = 0.0f;   // hi*lo
            float s0 = 0.0f, s1 = 0.0f, s2 = 0.0f, s3 = 0.0f;   // lo*hi
            const uint4* bnt = bp + nt * 8 * 32 + lid;
            #pragma unroll
            for (int kt = 0; kt < 8; kt++) {
                uint4 b = bnt[kt * 32];
                mma_bf16(p0, p1, p2, p3, ahi[kt][0], ahi[kt][1], ahi[kt][2], ahi[kt][3], b.x, b.y);
                mma_bf16(q0, q1, q2, q3, ahi[kt][0], ahi[kt][1], ahi[kt][2], ahi[kt][3], b.z, b.w);
                mma_bf16(s0, s1, s2, s3, alo[kt][0], alo[kt][1], alo[kt][2], alo[kt][3], b.x, b.y);
            }
            float d0 = p0 + q0 + s0, d1 = p1 + q1 + s1;
            float d2 = p2 + q2 + s2, d3 = p3 + q3 + s3;
            // epilogue fold: cols c = nt*8+2tq, c+1
            const int c = nt * 8 + 2 * tq;
            float4 wA = qrw2[c], wB = qrw2[c + 1];
            float hA0 = fmaxf(d0 + wA.w, 0.0f);
            float hA1 = fmaxf(d1 + wB.w, 0.0f);
            float hB0 = fmaxf(d2 + wA.w, 0.0f);
            float hB1 = fmaxf(d3 + wB.w, 0.0f);
            a00 = fmaf(hA0, wA.x, fmaf(hA1, wB.x, a00));
            a01 = fmaf(hA0, wA.y, fmaf(hA1, wB.y, a01));
            a02 = fmaf(hA0, wA.z, fmaf(hA1, wB.z, a02));
            a10 = fmaf(hB0, wA.x, fmaf(hB1, wB.x, a10));
            a11 = fmaf(hB0, wA.y, fmaf(hB1, wB.y, a11));
            a12 = fmaf(hB0, wA.z, fmaf(hB1, wB.z, a12));
        }
        // quad reduce (tq lanes hold disjoint col subsets of the same rows)
        #pragma unroll
        for (int d = 1; d <= 2; d <<= 1) {
            a00 += __shfl_xor_sync(0xffffffffu, a00, d);
            a01 += __shfl_xor_sync(0xffffffffu, a01, d);
            a02 += __shfl_xor_sync(0xffffffffu, a02, d);
            a10 += __shfl_xor_sync(0xffffffffu, a10, d);
            a11 += __shfl_xor_sync(0xffffffffu, a11, d);
            a12 += __shfl_xor_sync(0xffffffffu, a12, d);
        }
        if (tq == 0) {
            const float rb0  = ((const float*)(smdyn + SM_MISC))[0];
            const float rb1  = ((const float*)(smdyn + SM_MISC))[1];
            const float rb2v = ((const float*)(smdyn + SM_MISC))[2];
            rgb0 += w0 / (1.0f + expf(-(a00 + rb0)))  + w1 / (1.0f + expf(-(a10 + rb0)));
            rgb1 += w0 / (1.0f + expf(-(a01 + rb1)))  + w1 / (1.0f + expf(-(a11 + rb1)));
            rgb2 += w0 / (1.0f + expf(-(a02 + rb2v))) + w1 / (1.0f + expf(-(a12 + rb2v)));
        }
    }

    // ---- deterministic block reduction ----
    #pragma unroll
    for (int off = 16; off > 0; off >>= 1) {
        rgb0 += __shfl_down_sync(0xffffffffu, rgb0, off);
        rgb1 += __shfl_down_sync(0xffffffffu, rgb1, off);
        rgb2 += __shfl_down_sync(0xffffffffu, rgb2, off);
    }
    if (lid == 0) { wred[wid][0] = rgb0; wred[wid][1] = rgb1; wred[wid][2] = rgb2; }
    __syncthreads();
    if (tid < 3) {
        float s = 0.0f;
        #pragma unroll
        for (int w = 0; w < 4; w++) s += wred[w][tid];
        out[ray * 3 + tid] = s;
    }
}

extern "C" void kernel_launch(void* const* d_in, const int* in_sizes, int n_in,
                              void* d_out, int out_size) {
    const float* rays_o = (const float*)d_in[0];
    const float* rays_d = (const float*)d_in[1];
    const float* grid   = (const float*)d_in[2];
    const float* f_w1   = (const float*)d_in[3];
    const float* f_b1   = (const float*)d_in[4];
    const float* f_w2   = (const float*)d_in[5];
    const float* f_b2   = (const float*)d_in[6];
    const float* s_w    = (const float*)d_in[7];
    const float* s_b    = (const float*)d_in[8];
    const float* r_w1   = (const float*)d_in[9];
    const float* r_b1   = (const float*)d_in[10];
    const float* r_w2   = (const float*)d_in[11];
    const float* r_b2   = (const float*)d_in[12];
    float* out = (float*)d_out;

    const int n_rays = in_sizes[0] / 3;

    prep_kernel<<<(2241 + 255) / 256, 256>>>(f_w2, f_b2, s_w, s_b, r_w1, r_b1);

    cudaFuncSetAttribute(nerf_render_kernel,
                         cudaFuncAttributeMaxDynamicSharedMemorySize, SMEM_BYTES);
    nerf_render_kernel<<<n_rays, 128, SMEM_BYTES>>>(
        rays_o, rays_d, grid, f_w1, f_b1, r_w1, r_w2, r_b2, out);
}

// round 7
// speedup vs baseline: 3.8662x; 1.0181x over previous
#include <cuda_runtime.h>
#include <cuda_bf16.h>
#include <math.h>

typedef unsigned int u32;

#define OPACITY_TH 0.01f
#define EARLY_TERM 1e-4f

// pack two floats to bf16x2: low16 = bf16(lo_f), high16 = bf16(hi_f)
__device__ __forceinline__ u32 cvt2(float hi_f, float lo_f) {
    u32 r; asm("cvt.rn.bf16x2.f32 %0, %1, %2;" : "=r"(r) : "f"(hi_f), "f"(lo_f)); return r;
}

__device__ __forceinline__ void mma_bf16(float& d0, float& d1, float& d2, float& d3,
                                         u32 a0, u32 a1, u32 a2, u32 a3,
                                         u32 b0, u32 b1) {
    asm volatile("mma.sync.aligned.m16n8k16.row.col.f32.bf16.bf16.f32 "
        "{%0,%1,%2,%3}, {%4,%5,%6,%7}, {%8,%9}, {%0,%1,%2,%3};"
        : "+f"(d0), "+f"(d1), "+f"(d2), "+f"(d3)
        : "r"(a0), "r"(a1), "r"(a2), "r"(a3), "r"(b0), "r"(b1));
}

// ---------------- precomputed globals (prep kernel output) ----------------
// B fragments for mma m16n8k16 (.col B): fid = nt*8+kt, lane l:
//   n = nt*8 + (l>>2), t = l&3, k0 = kt*16 + 2t
//   uint4 = { bhi(k0,k0+1), bhi(k0+8,k0+9), blo(k0,k0+1), blo(k0+8,k0+9) }
__device__ __align__(16) uint4 g_Bfrag[64 * 32];
__device__ float g_ws[128];      // f_w2[k,:]·s_w
__device__ float g_hconst[64];   // f_b2 @ r_w1[:64,:] + r_b1
__device__ float g_sconst[1];    // f_b2·s_w + s_b

__global__ void prep_kernel(const float* __restrict__ f_w2, const float* __restrict__ f_b2,
                            const float* __restrict__ s_w,  const float* __restrict__ s_b,
                            const float* __restrict__ r_w1, const float* __restrict__ r_b1)
{
    int i = blockIdx.x * blockDim.x + threadIdx.x;
    if (i < 2048) {
        int fid = i >> 5, lane = i & 31;
        int nt = fid >> 3, kt = fid & 7;
        int n = nt * 8 + (lane >> 2);
        int tq = lane & 3;
        int k0 = kt * 16 + 2 * tq;
        float v[4]; float lo[4];
        #pragma unroll
        for (int e = 0; e < 4; e++) {
            int k = k0 + (e >> 1) * 8 + (e & 1);   // k0, k0+1, k0+8, k0+9
            float s = 0.0f;
            #pragma unroll 8
            for (int t = 0; t < 64; t++) s += f_w2[k * 64 + t] * r_w1[t * 64 + n];
            __nv_bfloat16 bh = __float2bfloat16(s);
            v[e] = s;
            lo[e] = s - __bfloat162float(bh);
        }
        uint4 o;
        o.x = cvt2(v[1], v[0]);
        o.y = cvt2(v[3], v[2]);
        o.z = cvt2(lo[1], lo[0]);
        o.w = cvt2(lo[3], lo[2]);
        g_Bfrag[fid * 32 + lane] = o;
    } else if (i < 2176) {
        int k = i - 2048;
        float s = 0.0f;
        #pragma unroll 8
        for (int t = 0; t < 64; t++) s += f_w2[k * 64 + t] * s_w[t];
        g_ws[k] = s;
    } else if (i < 2240) {
        int j = i - 2176;
        float s = r_b1[j];
        #pragma unroll 8
        for (int t = 0; t < 64; t++) s += f_b2[t] * r_w1[t * 64 + j];
        g_hconst[j] = s;
    } else if (i == 2240) {
        float s = s_b[0];
        for (int t = 0; t < 64; t++) s += f_b2[t] * s_w[t];
        g_sconst[0] = s;
    }
}

// ---------------- dynamic shared layout (bytes) ----------------
#define SM_BFRAG 0        // 32KB uint4[2048]
#define SM_W1B   32768    // [128][4] f32: (w1x,w1y,w1z,b1)  2KB
#define SM_WS    34816    // ws[128] f32                     512B
#define SM_RW2   35328    // [64][4]: (rw2_0,rw2_1,rw2_2,hc) 1KB
#define SM_WBUF  36352    // weight[256] (0 if !mask2)       1KB
#define SM_MISC  37376    // [0..2]=r_b2 (+pad)
#define SMEM_BYTES 37392

__device__ __forceinline__ float tmap(float u) {
    return (u < 0.5f) ? 2.0f * u : 1.0f / (2.0f - 2.0f * u);
}

#define USTEP ((257.0f / 258.0f) / 256.0f)

__device__ __forceinline__ void ray_pos(int s, float ox, float oy, float oz,
                                        float dx, float dy, float dz,
                                        float& px, float& py, float& pz) {
    float tv = tmap((float)s * USTEP);
    px = ox + dx * tv; py = oy + dy * tv; pz = oz + dz * tv;
    float nrm = sqrtf(px * px + py * py + pz * pz);
    float cs = (nrm <= 1.0f) ? 0.5f : (2.0f - 1.0f / nrm) / nrm * 0.5f;
    px *= cs; py *= cs; pz *= cs;
}

__device__ __forceinline__ float sample_grid(const float* __restrict__ grid,
                                             float px, float py, float pz) {
    float ixf = ((px + 1.0f) * 128.0f - 1.0f) * 0.5f;
    float iyf = ((py + 1.0f) * 128.0f - 1.0f) * 0.5f;
    float izf = ((pz + 1.0f) * 128.0f - 1.0f) * 0.5f;
    float fx0 = floorf(ixf), fy0 = floorf(iyf), fz0 = floorf(izf);
    int ix0 = (int)fx0, iy0 = (int)fy0, iz0 = (int)fz0;
    float fx = ixf - fx0, fy = iyf - fy0, fz = izf - fz0;
    float occ = 0.0f;
    #pragma unroll
    for (int dzc = 0; dzc < 2; dzc++) {
        int cz = iz0 + dzc;
        if (cz < 0 || cz >= 128) continue;
        float wz = dzc ? fz : 1.0f - fz;
        #pragma unroll
        for (int dyc = 0; dyc < 2; dyc++) {
            int cy = iy0 + dyc;
            if (cy < 0 || cy >= 128) continue;
            float wy = dyc ? fy : 1.0f - fy;
            #pragma unroll
            for (int dxc = 0; dxc < 2; dxc++) {
                int cx = ix0 + dxc;
                if (cx < 0 || cx >= 128) continue;
                float wx = dxc ? fx : 1.0f - fx;
                occ += wz * wy * wx * __ldg(&grid[(cz << 14) + (cy << 7) + cx]);
            }
        }
    }
    return occ;
}

__global__ void __launch_bounds__(128, 4) nerf_render_kernel(
    const float* __restrict__ rays_o, const float* __restrict__ rays_d,
    const float* __restrict__ grid,
    const float* __restrict__ f_w1, const float* __restrict__ f_b1,
    const float* __restrict__ r_w1, const float* __restrict__ r_w2,
    const float* __restrict__ r_b2,
    float* __restrict__ out)
{
    extern __shared__ __align__(16) char smdyn[];
    __shared__ float wsumA[4], wsumB[4];
    __shared__ float wred[4][3];

    const int tid = threadIdx.x;
    const int wid = tid >> 5;
    const int lid = tid & 31;
    const int g   = lid >> 2;   // mma group id (row within tile)
    const int tq  = lid & 3;    // mma thread-in-group (col pair)
    const int ray = blockIdx.x;

    const float ox = __ldg(&rays_o[ray * 3 + 0]);
    const float oy = __ldg(&rays_o[ray * 3 + 1]);
    const float oz = __ldg(&rays_o[ray * 3 + 2]);
    const float dx = __ldg(&rays_d[ray * 3 + 0]);
    const float dy = __ldg(&rays_d[ray * 3 + 1]);
    const float dz = __ldg(&rays_d[ray * 3 + 2]);

    // ---- staging ----
    {
        uint4* dstB = (uint4*)(smdyn + SM_BFRAG);
        #pragma unroll
        for (int i = 0; i < 16; i++) dstB[tid + 128 * i] = g_Bfrag[tid + 128 * i];
        float* dw1b = (float*)(smdyn + SM_W1B);
        for (int i = tid; i < 512; i += 128) {
            int k = i >> 2, c = i & 3;
            dw1b[i] = (c < 3) ? f_w1[c * 128 + k] : f_b1[k];
        }
        ((float*)(smdyn + SM_WS))[tid] = g_ws[tid];
        if (tid < 64) {
            float hcv = g_hconst[tid]
                      + dx * r_w1[64 * 64 + tid]
                      + dy * r_w1[65 * 64 + tid]
                      + dz * r_w1[66 * 64 + tid];
            *(float4*)(smdyn + SM_RW2 + tid * 16) =
                make_float4(r_w2[tid * 3], r_w2[tid * 3 + 1], r_w2[tid * 3 + 2], hcv);
        }
        if (tid < 3) ((float*)(smdyn + SM_MISC))[tid] = r_b2[tid];
    }
    __syncthreads();

    const float4* w1bv = (const float4*)(smdyn + SM_W1B);
    const float*  wsf  = (const float*)(smdyn + SM_WS);
    const uint4*  bp   = (const uint4*)(smdyn + SM_BFRAG);
    const float4* qrw2 = (const float4*)(smdyn + SM_RW2);
    float*        wbuf = (float*)(smdyn + SM_WBUF);
    const float sconst = g_sconst[0];

    // ========== PHASE 1: sigma + scan + weights (thread t ~ samples t, t+128)
    {
        float tA  = tmap((float)tid * USTEP);
        float tA1 = tmap((float)(tid + 1) * USTEP);
        float tB  = tmap((float)(tid + 128) * USTEP);
        float tB1 = tmap((float)(tid + 129) * USTEP);
        float distA = tA1 - tA, distB = tB1 - tB;

        float pxA, pyA, pzA, pxB, pyB, pzB;
        ray_pos(tid, ox, oy, oz, dx, dy, dz, pxA, pyA, pzA);
        ray_pos(tid + 128, ox, oy, oz, dx, dy, dz, pxB, pyB, pzB);
        const bool mA = sample_grid(grid, pxA, pyA, pzA) > OPACITY_TH;
        const bool mB = sample_grid(grid, pxB, pyB, pzB) > OPACITY_TH;

        float preA = sconst, preB = sconst;
        if (mA || mB) {
            #pragma unroll 4
            for (int k = 0; k < 128; k++) {
                float4 w = w1bv[k];
                float ws = wsf[k];
                float hA = fmaxf(w.w + pxA * w.x + pyA * w.y + pzA * w.z, 0.0f);
                float hB = fmaxf(w.w + pxB * w.x + pyB * w.y + pzB * w.z, 0.0f);
                preA = fmaf(hA, ws, preA);
                preB = fmaf(hB, ws, preB);
            }
        }
        float sigmaA = mA ? ((preA > 20.0f) ? preA : log1pf(expf(preA))) : 0.0f;
        float sigmaB = mB ? ((preB > 20.0f) ? preB : log1pf(expf(preB))) : 0.0f;

        float aA = -sigmaA * distA;
        float aB = -sigmaB * distB;
        float incA = aA, incB = aB;
        #pragma unroll
        for (int off = 1; off < 32; off <<= 1) {
            float yA = __shfl_up_sync(0xffffffffu, incA, off);
            float yB = __shfl_up_sync(0xffffffffu, incB, off);
            if (lid >= off) { incA += yA; incB += yB; }
        }
        if (lid == 31) { wsumA[wid] = incA; wsumB[wid] = incB; }
        __syncthreads();
        float offA = 0.0f, offB = 0.0f, totalA = 0.0f;
        #pragma unroll
        for (int i = 0; i < 4; i++) {
            float vA = wsumA[i];
            totalA += vA;
            if (i < wid) { offA += vA; offB += wsumB[i]; }
        }
        float exclA = offA + incA - aA;
        float exclB = totalA + offB + incB - aB;
        float transA = expf(exclA), transB = expf(exclB);
        float weightA = transA * (1.0f - expf(aA));
        float weightB = transB * (1.0f - expf(aB));
        wbuf[tid]       = (mA && transA > EARLY_TERM) ? weightA : 0.0f;
        wbuf[tid + 128] = (mB && transB > EARLY_TERM) ? weightB : 0.0f;
    }
    __syncthreads();

    // ========== PHASE 2: gated MMA + in-register epilogue ====================
    // INTERLEAVED tile map: 16 tiles of 16 rows; warp w takes tiles w, w+4, w+8, w+12
    // so each warp gets an even mix of near (live) and far (dead) samples.
    float rgb0 = 0.0f, rgb1 = 0.0f, rgb2 = 0.0f;
    const float rb0  = ((const float*)(smdyn + SM_MISC))[0];
    const float rb1  = ((const float*)(smdyn + SM_MISC))[1];
    const float rb2v = ((const float*)(smdyn + SM_MISC))[2];

    #pragma unroll
    for (int mt = 0; mt < 4; mt++) {
        const int tt = wid + 4 * mt;          // tile index 0..15
        const int r0 = 16 * tt + g;
        const int r1 = r0 + 8;
        const float w0 = wbuf[r0];
        const float w1 = wbuf[r1];
        // skip whole 16-row tile if every weight is exactly zero (output identical)
        if (!__any_sync(0xffffffffu, (w0 != 0.0f) | (w1 != 0.0f))) continue;

        float px0, py0, pz0, px1, py1, pz1;
        ray_pos(r0, ox, oy, oz, dx, dy, dz, px0, py0, pz0);
        ray_pos(r1, ox, oy, oz, dx, dy, dz, px1, py1, pz1);

        // A fragments (hi + lo bf16 split)
        u32 ahi[8][4], alo[8][4];
        #pragma unroll
        for (int kt = 0; kt < 8; kt++) {
            const int k0 = kt * 16 + 2 * tq;
            float4 wa = w1bv[k0],     wb = w1bv[k0 + 1];
            float4 wc = w1bv[k0 + 8], wd = w1bv[k0 + 9];
            float h00 = fmaxf(wa.w + px0 * wa.x + py0 * wa.y + pz0 * wa.z, 0.0f);
            float h01 = fmaxf(wb.w + px0 * wb.x + py0 * wb.y + pz0 * wb.z, 0.0f);
            float h08 = fmaxf(wc.w + px0 * wc.x + py0 * wc.y + pz0 * wc.z, 0.0f);
            float h09 = fmaxf(wd.w + px0 * wd.x + py0 * wd.y + pz0 * wd.z, 0.0f);
            float h10 = fmaxf(wa.w + px1 * wa.x + py1 * wa.y + pz1 * wa.z, 0.0f);
            float h11 = fmaxf(wb.w + px1 * wb.x + py1 * wb.y + pz1 * wb.z, 0.0f);
            float h18 = fmaxf(wc.w + px1 * wc.x + py1 * wc.y + pz1 * wc.z, 0.0f);
            float h19 = fmaxf(wd.w + px1 * wd.x + py1 * wd.y + pz1 * wd.z, 0.0f);
            u32 x0 = cvt2(h01, h00);
            u32 x1 = cvt2(h11, h10);
            u32 x2 = cvt2(h09, h08);
            u32 x3 = cvt2(h19, h18);
            ahi[kt][0] = x0; ahi[kt][1] = x1; ahi[kt][2] = x2; ahi[kt][3] = x3;
            float f00 = __uint_as_float(x0 << 16), f01 = __uint_as_float(x0 & 0xFFFF0000u);
            float f10 = __uint_as_float(x1 << 16), f11 = __uint_as_float(x1 & 0xFFFF0000u);
            float f08 = __uint_as_float(x2 << 16), f09 = __uint_as_float(x2 & 0xFFFF0000u);
            float f18 = __uint_as_float(x3 << 16), f19 = __uint_as_float(x3 & 0xFFFF0000u);
            alo[kt][0] = cvt2(h01 - f01, h00 - f00);
            alo[kt][1] = cvt2(h11 - f11, h10 - f10);
            alo[kt][2] = cvt2(h09 - f09, h08 - f08);
            alo[kt][3] = cvt2(h19 - f19, h18 - f18);
        }

        float a00 = 0.0f, a01 = 0.0f, a02 = 0.0f;   // row r0 rgb pre-act
        float a10 = 0.0f, a11 = 0.0f, a12 = 0.0f;   // row r1
        #pragma unroll
        for (int nt = 0; nt < 8; nt++) {
            // three independent accumulator sets (short chains)
            float p0 = 0.0f, p1 = 0.0f, p2 = 0.0f, p3 = 0.0f;   // hi*hi
            float q0 = 0.0f, q1 = 0.0f, q2 = 0.0f, q3 = 0.0f;   // hi*lo
            float s0 = 0.0f, s1 = 0.0f, s2 = 0.0f, s3 = 0.0f;   // lo*hi
            const uint4* bnt = bp + nt * 8 * 32 + lid;
            #pragma unroll
            for (int kt = 0; kt < 8; kt++) {
                uint4 b = bnt[kt * 32];
                mma_bf16(p0, p1, p2, p3, ahi[kt][0], ahi[kt][1], ahi[kt][2], ahi[kt][3], b.x, b.y);
                mma_bf16(q0, q1, q2, q3, ahi[kt][0], ahi[kt][1], ahi[kt][2], ahi[kt][3], b.z, b.w);
                mma_bf16(s0, s1, s2, s3, alo[kt][0], alo[kt][1], alo[kt][2], alo[kt][3], b.x, b.y);
            }
            float d0 = p0 + q0 + s0, d1 = p1 + q1 + s1;
            float d2 = p2 + q2 + s2, d3 = p3 + q3 + s3;
            // epilogue fold: cols c = nt*8+2tq, c+1
            const int c = nt * 8 + 2 * tq;
            float4 wA = qrw2[c], wB = qrw2[c + 1];
            float hA0 = fmaxf(d0 + wA.w, 0.0f);
            float hA1 = fmaxf(d1 + wB.w, 0.0f);
            float hB0 = fmaxf(d2 + wA.w, 0.0f);
            float hB1 = fmaxf(d3 + wB.w, 0.0f);
            a00 = fmaf(hA0, wA.x, fmaf(hA1, wB.x, a00));
            a01 = fmaf(hA0, wA.y, fmaf(hA1, wB.y, a01));
            a02 = fmaf(hA0, wA.z, fmaf(hA1, wB.z, a02));
            a10 = fmaf(hB0, wA.x, fmaf(hB1, wB.x, a10));
            a11 = fmaf(hB0, wA.y, fmaf(hB1, wB.y, a11));
            a12 = fmaf(hB0, wA.z, fmaf(hB1, wB.z, a12));
        }
        // quad reduce (tq lanes hold disjoint col subsets of the same rows)
        #pragma unroll
        for (int d = 1; d <= 2; d <<= 1) {
            a00 += __shfl_xor_sync(0xffffffffu, a00, d);
            a01 += __shfl_xor_sync(0xffffffffu, a01, d);
            a02 += __shfl_xor_sync(0xffffffffu, a02, d);
            a10 += __shfl_xor_sync(0xffffffffu, a10, d);
            a11 += __shfl_xor_sync(0xffffffffu, a11, d);
            a12 += __shfl_xor_sync(0xffffffffu, a12, d);
        }
        if (tq == 0) {
            rgb0 += w0 / (1.0f + expf(-(a00 + rb0)))  + w1 / (1.0f + expf(-(a10 + rb0)));
            rgb1 += w0 / (1.0f + expf(-(a01 + rb1)))  + w1 / (1.0f + expf(-(a11 + rb1)));
            rgb2 += w0 / (1.0f + expf(-(a02 + rb2v))) + w1 / (1.0f + expf(-(a12 + rb2v)));
        }
    }

    // ---- deterministic block reduction ----
    #pragma unroll
    for (int off = 16; off > 0; off >>= 1) {
        rgb0 += __shfl_down_sync(0xffffffffu, rgb0, off);
        rgb1 += __shfl_down_sync(0xffffffffu, rgb1, off);
        rgb2 += __shfl_down_sync(0xffffffffu, rgb2, off);
    }
    if (lid == 0) { wred[wid][0] = rgb0; wred[wid][1] = rgb1; wred[wid][2] = rgb2; }
    __syncthreads();
    if (tid < 3) {
        float s = 0.0f;
        #pragma unroll
        for (int w = 0; w < 4; w++) s += wred[w][tid];
        out[ray * 3 + tid] = s;
    }
}

extern "C" void kernel_launch(void* const* d_in, const int* in_sizes, int n_in,
                              void* d_out, int out_size) {
    const float* rays_o = (const float*)d_in[0];
    const float* rays_d = (const float*)d_in[1];
    const float* grid   = (const float*)d_in[2];
    const float* f_w1   = (const float*)d_in[3];
    const float* f_b1   = (const float*)d_in[4];
    const float* f_w2   = (const float*)d_in[5];
    const float* f_b2   = (const float*)d_in[6];
    const float* s_w    = (const float*)d_in[7];
    const float* s_b    = (const float*)d_in[8];
    const float* r_w1   = (const float*)d_in[9];
    const float* r_b1   = (const float*)d_in[10];
    const float* r_w2   = (const float*)d_in[11];
    const float* r_b2   = (const float*)d_in[12];
    float* out = (float*)d_out;

    const int n_rays = in_sizes[0] / 3;

    prep_kernel<<<(2241 + 255) / 256, 256>>>(f_w2, f_b2, s_w, s_b, r_w1, r_b1);

    cudaFuncSetAttribute(nerf_render_kernel,
                         cudaFuncAttributeMaxDynamicSharedMemorySize, SMEM_BYTES);
    nerf_render_kernel<<<n_rays, 128, SMEM_BYTES>>>(
        rays_o, rays_d, grid, f_w1, f_b1, r_w1, r_w2, r_b2, out);
}

// round 8
// speedup vs baseline: 4.0814x; 1.0557x over previous
#include <cuda_runtime.h>
#include <cuda_bf16.h>
#include <math.h>

typedef unsigned int u32;

#define OPACITY_TH 0.01f
#define EARLY_TERM 1e-4f

// pack two floats to bf16x2: low16 = bf16(lo_f), high16 = bf16(hi_f)
__device__ __forceinline__ u32 cvt2(float hi_f, float lo_f) {
    u32 r; asm("cvt.rn.bf16x2.f32 %0, %1, %2;" : "=r"(r) : "f"(hi_f), "f"(lo_f)); return r;
}

__device__ __forceinline__ void mma_bf16(float& d0, float& d1, float& d2, float& d3,
                                         u32 a0, u32 a1, u32 a2, u32 a3,
                                         u32 b0, u32 b1) {
    asm volatile("mma.sync.aligned.m16n8k16.row.col.f32.bf16.bf16.f32 "
        "{%0,%1,%2,%3}, {%4,%5,%6,%7}, {%8,%9}, {%0,%1,%2,%3};"
        : "+f"(d0), "+f"(d1), "+f"(d2), "+f"(d3)
        : "r"(a0), "r"(a1), "r"(a2), "r"(a3), "r"(b0), "r"(b1));
}

// ---------------- precomputed globals (prep kernel output) ----------------
__device__ __align__(16) uint4 g_Bfrag[64 * 32];
__device__ float g_ws[128];      // f_w2[k,:]·s_w
__device__ float g_hconst[64];   // f_b2 @ r_w1[:64,:] + r_b1
__device__ float g_sconst[1];    // f_b2·s_w + s_b

__global__ void prep_kernel(const float* __restrict__ f_w2, const float* __restrict__ f_b2,
                            const float* __restrict__ s_w,  const float* __restrict__ s_b,
                            const float* __restrict__ r_w1, const float* __restrict__ r_b1)
{
    int i = blockIdx.x * blockDim.x + threadIdx.x;
    if (i < 2048) {
        int fid = i >> 5, lane = i & 31;
        int nt = fid >> 3, kt = fid & 7;
        int n = nt * 8 + (lane >> 2);
        int tq = lane & 3;
        int k0 = kt * 16 + 2 * tq;
        float v[4]; float lo[4];
        #pragma unroll
        for (int e = 0; e < 4; e++) {
            int k = k0 + (e >> 1) * 8 + (e & 1);   // k0, k0+1, k0+8, k0+9
            float s = 0.0f;
            #pragma unroll 8
            for (int t = 0; t < 64; t++) s += f_w2[k * 64 + t] * r_w1[t * 64 + n];
            __nv_bfloat16 bh = __float2bfloat16(s);
            v[e] = s;
            lo[e] = s - __bfloat162float(bh);
        }
        uint4 o;
        o.x = cvt2(v[1], v[0]);
        o.y = cvt2(v[3], v[2]);
        o.z = cvt2(lo[1], lo[0]);
        o.w = cvt2(lo[3], lo[2]);
        g_Bfrag[fid * 32 + lane] = o;
    } else if (i < 2176) {
        int k = i - 2048;
        float s = 0.0f;
        #pragma unroll 8
        for (int t = 0; t < 64; t++) s += f_w2[k * 64 + t] * s_w[t];
        g_ws[k] = s;
    } else if (i < 2240) {
        int j = i - 2176;
        float s = r_b1[j];
        #pragma unroll 8
        for (int t = 0; t < 64; t++) s += f_b2[t] * r_w1[t * 64 + j];
        g_hconst[j] = s;
    } else if (i == 2240) {
        float s = s_b[0];
        for (int t = 0; t < 64; t++) s += f_b2[t] * s_w[t];
        g_sconst[0] = s;
    }
}

// ---------------- dynamic shared layout (bytes) ----------------
#define SM_BFRAG 0        // 32KB uint4[2048]
#define SM_W1B   32768    // [128][4] f32                    2KB
#define SM_WS    34816    // ws[128] f32                     512B
#define SM_RW2   35328    // [64][4]: (rw2_0,rw2_1,rw2_2,hc) 1KB
#define SM_SIGB  36352    // sigma_pre[256]                  1KB
#define SM_RGBB  37376    // rgbRaw[256] float4              4KB
#define SM_MISC  41472    // [0..2]=r_b2, [3]=sconst
#define SMEM_BYTES 41488

__device__ __forceinline__ float tmap(float u) {
    return (u < 0.5f) ? 2.0f * u : 1.0f / (2.0f - 2.0f * u);
}

#define USTEP ((257.0f / 258.0f) / 256.0f)

__device__ __forceinline__ void ray_pos(int s, float ox, float oy, float oz,
                                        float dx, float dy, float dz,
                                        float& px, float& py, float& pz) {
    float tv = tmap((float)s * USTEP);
    px = ox + dx * tv; py = oy + dy * tv; pz = oz + dz * tv;
    float nrm = sqrtf(px * px + py * py + pz * pz);
    float cs = (nrm <= 1.0f) ? 0.5f : (2.0f - 1.0f / nrm) / nrm * 0.5f;
    px *= cs; py *= cs; pz *= cs;
}

__device__ __forceinline__ float sample_grid(const float* __restrict__ grid,
                                             float px, float py, float pz) {
    float ixf = ((px + 1.0f) * 128.0f - 1.0f) * 0.5f;
    float iyf = ((py + 1.0f) * 128.0f - 1.0f) * 0.5f;
    float izf = ((pz + 1.0f) * 128.0f - 1.0f) * 0.5f;
    float fx0 = floorf(ixf), fy0 = floorf(iyf), fz0 = floorf(izf);
    int ix0 = (int)fx0, iy0 = (int)fy0, iz0 = (int)fz0;
    float fx = ixf - fx0, fy = iyf - fy0, fz = izf - fz0;
    float occ = 0.0f;
    #pragma unroll
    for (int dzc = 0; dzc < 2; dzc++) {
        int cz = iz0 + dzc;
        if (cz < 0 || cz >= 128) continue;
        float wz = dzc ? fz : 1.0f - fz;
        #pragma unroll
        for (int dyc = 0; dyc < 2; dyc++) {
            int cy = iy0 + dyc;
            if (cy < 0 || cy >= 128) continue;
            float wy = dyc ? fy : 1.0f - fy;
            #pragma unroll
            for (int dxc = 0; dxc < 2; dxc++) {
                int cx = ix0 + dxc;
                if (cx < 0 || cx >= 128) continue;
                float wx = dxc ? fx : 1.0f - fx;
                occ += wz * wy * wx * __ldg(&grid[(cz << 14) + (cy << 7) + cx]);
            }
        }
    }
    return occ;
}

__global__ void __launch_bounds__(128, 4) nerf_render_kernel(
    const float* __restrict__ rays_o, const float* __restrict__ rays_d,
    const float* __restrict__ grid,
    const float* __restrict__ f_w1, const float* __restrict__ f_b1,
    const float* __restrict__ r_w1, const float* __restrict__ r_w2,
    const float* __restrict__ r_b2,
    float* __restrict__ out)
{
    extern __shared__ __align__(16) char smdyn[];
    __shared__ float wsumA[4], wsumB[4];
    __shared__ float wred[4][3];

    const int tid = threadIdx.x;
    const int wid = tid >> 5;
    const int lid = tid & 31;
    const int g   = lid >> 2;   // mma row-in-tile
    const int tq  = lid & 3;    // mma col-pair
    const int ray = blockIdx.x;

    const float ox = __ldg(&rays_o[ray * 3 + 0]);
    const float oy = __ldg(&rays_o[ray * 3 + 1]);
    const float oz = __ldg(&rays_o[ray * 3 + 2]);
    const float dx = __ldg(&rays_d[ray * 3 + 0]);
    const float dy = __ldg(&rays_d[ray * 3 + 1]);
    const float dz = __ldg(&rays_d[ray * 3 + 2]);

    // ---- staging ----
    {
        uint4* dstB = (uint4*)(smdyn + SM_BFRAG);
        #pragma unroll
        for (int i = 0; i < 16; i++) dstB[tid + 128 * i] = g_Bfrag[tid + 128 * i];
        float* dw1b = (float*)(smdyn + SM_W1B);
        for (int i = tid; i < 512; i += 128) {
            int k = i >> 2, c = i & 3;
            dw1b[i] = (c < 3) ? f_w1[c * 128 + k] : f_b1[k];
        }
        ((float*)(smdyn + SM_WS))[tid] = g_ws[tid];
        if (tid < 64) {
            float hcv = g_hconst[tid]
                      + dx * r_w1[64 * 64 + tid]
                      + dy * r_w1[65 * 64 + tid]
                      + dz * r_w1[66 * 64 + tid];
            *(float4*)(smdyn + SM_RW2 + tid * 16) =
                make_float4(r_w2[tid * 3], r_w2[tid * 3 + 1], r_w2[tid * 3 + 2], hcv);
        }
        if (tid < 3)  ((float*)(smdyn + SM_MISC))[tid] = r_b2[tid];
        if (tid == 3) ((float*)(smdyn + SM_MISC))[3] = g_sconst[0];
    }
    __syncthreads();

    const float4* w1bv = (const float4*)(smdyn + SM_W1B);
    const float*  wsf  = (const float*)(smdyn + SM_WS);
    const uint4*  bp   = (const uint4*)(smdyn + SM_BFRAG);
    const float4* qrw2 = (const float4*)(smdyn + SM_RW2);
    float*        sigb = (float*)(smdyn + SM_SIGB);
    float4*       rgbb = (float4*)(smdyn + SM_RGBB);
    const float rb0  = ((const float*)(smdyn + SM_MISC))[0];
    const float rb1  = ((const float*)(smdyn + SM_MISC))[1];
    const float rb2v = ((const float*)(smdyn + SM_MISC))[2];
    const float sconst = ((const float*)(smdyn + SM_MISC))[3];

    // ========== PHASE A: h build + sigma-dot + MMA + weight-free epilogue ====
    // warp wid owns tiles wid*4 .. wid*4+3 (16 rows each); no gating (masks ~all true)
    #pragma unroll
    for (int mt = 0; mt < 4; mt++) {
        const int tt = wid * 4 + mt;
        const int r0 = 16 * tt + g;
        const int r1 = r0 + 8;

        float px0, py0, pz0, px1, py1, pz1;
        ray_pos(r0, ox, oy, oz, dx, dy, dz, px0, py0, pz0);
        ray_pos(r1, ox, oy, oz, dx, dy, dz, px1, py1, pz1);

        // A fragments (hi + lo bf16 split) + sigma-dot partials
        u32 ahi[8][4], alo[8][4];
        float sp0 = 0.0f, sp1 = 0.0f;
        #pragma unroll
        for (int kt = 0; kt < 8; kt++) {
            const int k0 = kt * 16 + 2 * tq;
            float4 wa = w1bv[k0],     wb = w1bv[k0 + 1];
            float4 wc = w1bv[k0 + 8], wd = w1bv[k0 + 9];
            float h00 = fmaxf(wa.w + px0 * wa.x + py0 * wa.y + pz0 * wa.z, 0.0f);
            float h01 = fmaxf(wb.w + px0 * wb.x + py0 * wb.y + pz0 * wb.z, 0.0f);
            float h08 = fmaxf(wc.w + px0 * wc.x + py0 * wc.y + pz0 * wc.z, 0.0f);
            float h09 = fmaxf(wd.w + px0 * wd.x + py0 * wd.y + pz0 * wd.z, 0.0f);
            float h10 = fmaxf(wa.w + px1 * wa.x + py1 * wa.y + pz1 * wa.z, 0.0f);
            float h11 = fmaxf(wb.w + px1 * wb.x + py1 * wb.y + pz1 * wb.z, 0.0f);
            float h18 = fmaxf(wc.w + px1 * wc.x + py1 * wc.y + pz1 * wc.z, 0.0f);
            float h19 = fmaxf(wd.w + px1 * wd.x + py1 * wd.y + pz1 * wd.z, 0.0f);
            float2 wsa = *(const float2*)&wsf[k0];
            float2 wsb = *(const float2*)&wsf[k0 + 8];
            sp0 = fmaf(h00, wsa.x, fmaf(h01, wsa.y, fmaf(h08, wsb.x, fmaf(h09, wsb.y, sp0))));
            sp1 = fmaf(h10, wsa.x, fmaf(h11, wsa.y, fmaf(h18, wsb.x, fmaf(h19, wsb.y, sp1))));
            u32 x0 = cvt2(h01, h00);
            u32 x1 = cvt2(h11, h10);
            u32 x2 = cvt2(h09, h08);
            u32 x3 = cvt2(h19, h18);
            ahi[kt][0] = x0; ahi[kt][1] = x1; ahi[kt][2] = x2; ahi[kt][3] = x3;
            float f00 = __uint_as_float(x0 << 16), f01 = __uint_as_float(x0 & 0xFFFF0000u);
            float f10 = __uint_as_float(x1 << 16), f11 = __uint_as_float(x1 & 0xFFFF0000u);
            float f08 = __uint_as_float(x2 << 16), f09 = __uint_as_float(x2 & 0xFFFF0000u);
            float f18 = __uint_as_float(x3 << 16), f19 = __uint_as_float(x3 & 0xFFFF0000u);
            alo[kt][0] = cvt2(h01 - f01, h00 - f00);
            alo[kt][1] = cvt2(h11 - f11, h10 - f10);
            alo[kt][2] = cvt2(h09 - f09, h08 - f08);
            alo[kt][3] = cvt2(h19 - f19, h18 - f18);
        }
        // sigma-dot quad reduce (tq lanes hold disjoint k subsets)
        sp0 += __shfl_xor_sync(0xffffffffu, sp0, 1);
        sp0 += __shfl_xor_sync(0xffffffffu, sp0, 2);
        sp1 += __shfl_xor_sync(0xffffffffu, sp1, 1);
        sp1 += __shfl_xor_sync(0xffffffffu, sp1, 2);
        if (tq == 0) { sigb[r0] = sp0; sigb[r1] = sp1; }

        float a00 = 0.0f, a01 = 0.0f, a02 = 0.0f;   // row r0 rgb pre-act
        float a10 = 0.0f, a11 = 0.0f, a12 = 0.0f;   // row r1
        #pragma unroll
        for (int nt = 0; nt < 8; nt++) {
            float p0 = 0.0f, p1 = 0.0f, p2 = 0.0f, p3 = 0.0f;   // hi*hi
            float q0 = 0.0f, q1 = 0.0f, q2 = 0.0f, q3 = 0.0f;   // hi*lo
            float s0 = 0.0f, s1 = 0.0f, s2 = 0.0f, s3 = 0.0f;   // lo*hi
            const uint4* bnt = bp + nt * 8 * 32 + lid;
            #pragma unroll
            for (int kt = 0; kt < 8; kt++) {
                uint4 b = bnt[kt * 32];
                mma_bf16(p0, p1, p2, p3, ahi[kt][0], ahi[kt][1], ahi[kt][2], ahi[kt][3], b.x, b.y);
                mma_bf16(q0, q1, q2, q3, ahi[kt][0], ahi[kt][1], ahi[kt][2], ahi[kt][3], b.z, b.w);
                mma_bf16(s0, s1, s2, s3, alo[kt][0], alo[kt][1], alo[kt][2], alo[kt][3], b.x, b.y);
            }
            float d0 = p0 + q0 + s0, d1 = p1 + q1 + s1;
            float d2 = p2 + q2 + s2, d3 = p3 + q3 + s3;
            const int c = nt * 8 + 2 * tq;
            float4 wA = qrw2[c], wB = qrw2[c + 1];
            float hA0 = fmaxf(d0 + wA.w, 0.0f);
            float hA1 = fmaxf(d1 + wB.w, 0.0f);
            float hB0 = fmaxf(d2 + wA.w, 0.0f);
            float hB1 = fmaxf(d3 + wB.w, 0.0f);
            a00 = fmaf(hA0, wA.x, fmaf(hA1, wB.x, a00));
            a01 = fmaf(hA0, wA.y, fmaf(hA1, wB.y, a01));
            a02 = fmaf(hA0, wA.z, fmaf(hA1, wB.z, a02));
            a10 = fmaf(hB0, wA.x, fmaf(hB1, wB.x, a10));
            a11 = fmaf(hB0, wA.y, fmaf(hB1, wB.y, a11));
            a12 = fmaf(hB0, wA.z, fmaf(hB1, wB.z, a12));
        }
        #pragma unroll
        for (int d = 1; d <= 2; d <<= 1) {
            a00 += __shfl_xor_sync(0xffffffffu, a00, d);
            a01 += __shfl_xor_sync(0xffffffffu, a01, d);
            a02 += __shfl_xor_sync(0xffffffffu, a02, d);
            a10 += __shfl_xor_sync(0xffffffffu, a10, d);
            a11 += __shfl_xor_sync(0xffffffffu, a11, d);
            a12 += __shfl_xor_sync(0xffffffffu, a12, d);
        }
        if (tq == 0) {
            // weight-independent per-sample color (sigmoid commutes past weighting)
            rgbb[r0] = make_float4(1.0f / (1.0f + expf(-(a00 + rb0))),
                                   1.0f / (1.0f + expf(-(a01 + rb1))),
                                   1.0f / (1.0f + expf(-(a02 + rb2v))), 0.0f);
            rgbb[r1] = make_float4(1.0f / (1.0f + expf(-(a10 + rb0))),
                                   1.0f / (1.0f + expf(-(a11 + rb1))),
                                   1.0f / (1.0f + expf(-(a12 + rb2v))), 0.0f);
        }
    }
    __syncthreads();

    // ========== PHASE B: masks + scan + weighted accumulation ================
    float rgb0, rgb1, rgb2;
    {
        float tA  = tmap((float)tid * USTEP);
        float tA1 = tmap((float)(tid + 1) * USTEP);
        float tB  = tmap((float)(tid + 128) * USTEP);
        float tB1 = tmap((float)(tid + 129) * USTEP);
        float distA = tA1 - tA, distB = tB1 - tB;

        float pxA, pyA, pzA, pxB, pyB, pzB;
        ray_pos(tid, ox, oy, oz, dx, dy, dz, pxA, pyA, pzA);
        ray_pos(tid + 128, ox, oy, oz, dx, dy, dz, pxB, pyB, pzB);
        const bool mA = sample_grid(grid, pxA, pyA, pzA) > OPACITY_TH;
        const bool mB = sample_grid(grid, pxB, pyB, pzB) > OPACITY_TH;

        float preA = sigb[tid] + sconst;
        float preB = sigb[tid + 128] + sconst;
        float sigmaA = mA ? ((preA > 20.0f) ? preA : log1pf(expf(preA))) : 0.0f;
        float sigmaB = mB ? ((preB > 20.0f) ? preB : log1pf(expf(preB))) : 0.0f;

        float aA = -sigmaA * distA;
        float aB = -sigmaB * distB;
        float incA = aA, incB = aB;
        #pragma unroll
        for (int off = 1; off < 32; off <<= 1) {
            float yA = __shfl_up_sync(0xffffffffu, incA, off);
            float yB = __shfl_up_sync(0xffffffffu, incB, off);
            if (lid >= off) { incA += yA; incB += yB; }
        }
        if (lid == 31) { wsumA[wid] = incA; wsumB[wid] = incB; }
        __syncthreads();
        float offA = 0.0f, offB = 0.0f, totalA = 0.0f;
        #pragma unroll
        for (int i = 0; i < 4; i++) {
            float vA = wsumA[i];
            totalA += vA;
            if (i < wid) { offA += vA; offB += wsumB[i]; }
        }
        float exclA = offA + incA - aA;
        float exclB = totalA + offB + incB - aB;
        float transA = expf(exclA), transB = expf(exclB);
        float weightA = transA * (1.0f - expf(aA));
        float weightB = transB * (1.0f - expf(aB));
        float wA = (mA && transA > EARLY_TERM) ? weightA : 0.0f;
        float wB = (mB && transB > EARLY_TERM) ? weightB : 0.0f;

        float4 cA = rgbb[tid];
        float4 cB = rgbb[tid + 128];
        rgb0 = wA * cA.x + wB * cB.x;
        rgb1 = wA * cA.y + wB * cB.y;
        rgb2 = wA * cA.z + wB * cB.z;
    }

    // ---- deterministic block reduction ----
    #pragma unroll
    for (int off = 16; off > 0; off >>= 1) {
        rgb0 += __shfl_down_sync(0xffffffffu, rgb0, off);
        rgb1 += __shfl_down_sync(0xffffffffu, rgb1, off);
        rgb2 += __shfl_down_sync(0xffffffffu, rgb2, off);
    }
    if (lid == 0) { wred[wid][0] = rgb0; wred[wid][1] = rgb1; wred[wid][2] = rgb2; }
    __syncthreads();
    if (tid < 3) {
        float s = 0.0f;
        #pragma unroll
        for (int w = 0; w < 4; w++) s += wred[w][tid];
        out[ray * 3 + tid] = s;
    }
}

extern "C" void kernel_launch(void* const* d_in, const int* in_sizes, int n_in,
                              void* d_out, int out_size) {
    const float* rays_o = (const float*)d_in[0];
    const float* rays_d = (const float*)d_in[1];
    const float* grid   = (const float*)d_in[2];
    const float* f_w1   = (const float*)d_in[3];
    const float* f_b1   = (const float*)d_in[4];
    const float* f_w2   = (const float*)d_in[5];
    const float* f_b2   = (const float*)d_in[6];
    const float* s_w    = (const float*)d_in[7];
    const float* s_b    = (const float*)d_in[8];
    const float* r_w1   = (const float*)d_in[9];
    const float* r_b1   = (const float*)d_in[10];
    const float* r_w2   = (const float*)d_in[11];
    const float* r_b2   = (const float*)d_in[12];
    float* out = (float*)d_out;

    const int n_rays = in_sizes[0] / 3;

    prep_kernel<<<(2241 + 255) / 256, 256>>>(f_w2, f_b2, s_w, s_b, r_w1, r_b1);

    cudaFuncSetAttribute(nerf_render_kernel,
                         cudaFuncAttributeMaxDynamicSharedMemorySize, SMEM_BYTES);
    nerf_render_kernel<<<n_rays, 128, SMEM_BYTES>>>(
        rays_o, rays_d, grid, f_w1, f_b1, r_w1, r_w2, r_b2, out);
}